// round 5
// baseline (speedup 1.0000x reference)
#include <cuda_runtime.h>
#include <math.h>
#include <stdint.h>

#define T_TOK 16384
#define H_DIM 2048
#define E_NUM 16
#define I_DIM 1408
#define TWOI  2816
#define S_SLOTS (T_TOK*2)

// ---------------- scratch (device globals: no allocations allowed) ----------
__device__ int   g_counts[E_NUM];
__device__ int   g_fill[E_NUM];
__device__ int   g_offs[E_NUM+1];
__device__ int   g_ids[S_SLOTS];
__device__ float g_topw[S_SLOTS];
__device__ int   g_perm[S_SLOTS];          // slot -> token
__device__ int   g_slot[S_SLOTS];          // (token,k) -> slot
__device__ float g_gbuf[(size_t)S_SLOTS * TWOI];   // g = x @ w13^T
__device__ float g_actb[(size_t)S_SLOTS * I_DIM];  // silu(g1)*g2
__device__ float g_ybuf[(size_t)S_SLOTS * H_DIM];  // act @ w2^T

// ---------------- routing ---------------------------------------------------
__global__ void init_kernel() {
    int i = threadIdx.x;
    if (i < E_NUM) { g_counts[i] = 0; g_fill[i] = 0; }
}

__global__ void route_kernel(const float* __restrict__ logits) {
    int t = blockIdx.x * blockDim.x + threadIdx.x;
    if (t >= T_TOK) return;
    float l[E_NUM];
#pragma unroll
    for (int e = 0; e < E_NUM; e++) l[e] = logits[t * E_NUM + e];
    int e0 = 0; float m0 = l[0];
#pragma unroll
    for (int e = 1; e < E_NUM; e++) if (l[e] > m0) { m0 = l[e]; e0 = e; }
    int e1 = -1; float m1 = -1e30f;
#pragma unroll
    for (int e = 0; e < E_NUM; e++) if (e != e0 && l[e] > m1) { m1 = l[e]; e1 = e; }
    float w0 = 1.f / (1.f + expf(m1 - m0));   // renormalized top-2 softmax
    float w1 = 1.f - w0;
    g_ids[2*t] = e0;  g_ids[2*t+1] = e1;
    g_topw[2*t] = w0; g_topw[2*t+1] = w1;
    atomicAdd(&g_counts[e0], 1);
    atomicAdd(&g_counts[e1], 1);
}

__global__ void scan_kernel() {
    if (threadIdx.x == 0) {
        int acc = 0; g_offs[0] = 0;
        for (int e = 0; e < E_NUM; e++) { acc += g_counts[e]; g_offs[e+1] = acc; }
    }
}

__global__ void perm_kernel() {
    int t = blockIdx.x * blockDim.x + threadIdx.x;
    if (t >= T_TOK) return;
#pragma unroll
    for (int s = 0; s < 2; s++) {
        int e = g_ids[2*t+s];
        int pos = g_offs[e] + atomicAdd(&g_fill[e], 1);
        g_perm[pos] = t;
        g_slot[2*t+s] = pos;
    }
}

// ---------------- tf32 mma helpers ------------------------------------------
__device__ __forceinline__ uint32_t f2tf(float x) {
    uint32_t r; asm("cvt.rna.tf32.f32 %0, %1;" : "=r"(r) : "f"(x)); return r;
}
__device__ __forceinline__ void mma8(float* c, const uint32_t* a, const uint32_t* b) {
    asm volatile(
        "mma.sync.aligned.m16n8k8.row.col.f32.tf32.tf32.f32 "
        "{%0,%1,%2,%3},{%4,%5,%6,%7},{%8,%9},{%0,%1,%2,%3};"
        : "+f"(c[0]), "+f"(c[1]), "+f"(c[2]), "+f"(c[3])
        : "r"(a[0]), "r"(a[1]), "r"(a[2]), "r"(a[3]), "r"(b[0]), "r"(b[1]));
}

// ---------------- grouped GEMM: C[slot, n] = A[slot,:] . B_e[n,:] ------------
// 128x128x16 CTA tile, 128 threads, 4 warps of 64x64.
// smem holds tf32-converted bits: cvt once on store, plain LDS on fragment load.
#define LDG_TILE(kt) {                                                   \
    const float4* ap_ = (const float4*)(arow + (kt)*16);                 \
    const float4* bp_ = (const float4*)(brow + (kt)*16);                 \
    ra0 = ap_[0]; ra1 = ap_[1]; ra2 = ap_[2]; ra3 = ap_[3];              \
    rb0 = bp_[0]; rb1 = bp_[1]; rb2 = bp_[2]; rb3 = bp_[3]; }

#define STS_TILE(buf) {                                                  \
    uint32_t* as_ = &As[buf][0][lrow];                                   \
    uint32_t* bs_ = &Bs[buf][0][lrow];                                   \
    as_[ 0*136]=f2tf(ra0.x); as_[ 1*136]=f2tf(ra0.y);                    \
    as_[ 2*136]=f2tf(ra0.z); as_[ 3*136]=f2tf(ra0.w);                    \
    as_[ 4*136]=f2tf(ra1.x); as_[ 5*136]=f2tf(ra1.y);                    \
    as_[ 6*136]=f2tf(ra1.z); as_[ 7*136]=f2tf(ra1.w);                    \
    as_[ 8*136]=f2tf(ra2.x); as_[ 9*136]=f2tf(ra2.y);                    \
    as_[10*136]=f2tf(ra2.z); as_[11*136]=f2tf(ra2.w);                    \
    as_[12*136]=f2tf(ra3.x); as_[13*136]=f2tf(ra3.y);                    \
    as_[14*136]=f2tf(ra3.z); as_[15*136]=f2tf(ra3.w);                    \
    bs_[ 0*136]=f2tf(rb0.x); bs_[ 1*136]=f2tf(rb0.y);                    \
    bs_[ 2*136]=f2tf(rb0.z); bs_[ 3*136]=f2tf(rb0.w);                    \
    bs_[ 4*136]=f2tf(rb1.x); bs_[ 5*136]=f2tf(rb1.y);                    \
    bs_[ 6*136]=f2tf(rb1.z); bs_[ 7*136]=f2tf(rb1.w);                    \
    bs_[ 8*136]=f2tf(rb2.x); bs_[ 9*136]=f2tf(rb2.y);                    \
    bs_[10*136]=f2tf(rb2.z); bs_[11*136]=f2tf(rb2.w);                    \
    bs_[12*136]=f2tf(rb3.x); bs_[13*136]=f2tf(rb3.y);                    \
    bs_[14*136]=f2tf(rb3.z); bs_[15*136]=f2tf(rb3.w); }

template<int KDIM, int NB, int CLD, bool G1>
__global__ __launch_bounds__(128, 2) void moe_gemm(
    const float* __restrict__ Aext, const float* __restrict__ Bext)
{
    int e     = blockIdx.z;
    int off   = g_offs[e];
    int cnt   = g_offs[e+1] - off;
    int mbase = blockIdx.y * 128;
    if (mbase >= cnt) return;
    int rowsValid = cnt - mbase;                 // rows in this tile (<=128)
    int slot0 = off + mbase;
    int nbase = blockIdx.x * 128;

    __shared__ uint32_t As[2][16][136];          // [k][m] tf32 bits, +8 pad
    __shared__ uint32_t Bs[2][16][136];          // [k][n]

    int tid  = threadIdx.x;
    int lrow = tid;                              // 0..127: one row per thread

    int slot = slot0 + lrow;
    if (slot > S_SLOTS - 1) slot = S_SLOTS - 1;  // clamp; stores masked anyway
    const float* arow = G1 ? (Aext + (size_t)g_perm[slot] * KDIM)
                           : (&g_actb[(size_t)slot * KDIM]);
    const float* brow = Bext + ((size_t)e * NB + nbase + lrow) * KDIM;
    float* Cbase = G1 ? g_gbuf : g_ybuf;

    int lane = tid & 31;
    int warp = tid >> 5;
    int wm = (warp & 1) * 64;                    // 2x2 warp grid, 64x64 tiles
    int wn = (warp >> 1) * 64;
    int tr = lane >> 2;                          // groupID 0..7
    int tc = lane & 3;                           // thread-in-group 0..3

    float acc[4][8][4];
#pragma unroll
    for (int a = 0; a < 4; a++)
#pragma unroll
        for (int b = 0; b < 8; b++)
#pragma unroll
            for (int c = 0; c < 4; c++) acc[a][b][c] = 0.f;

    float4 ra0, ra1, ra2, ra3, rb0, rb1, rb2, rb3;
    constexpr int NK = KDIM / 16;

    LDG_TILE(0);
    STS_TILE(0);
    __syncthreads();

    for (int kt = 0; kt < NK; kt++) {
        int cur = kt & 1;
        if (kt + 1 < NK) LDG_TILE(kt + 1);       // global prefetch over compute
#pragma unroll
        for (int ks = 0; ks < 2; ks++) {
            int kb = ks * 8;
            uint32_t af[4][4], bf[8][2];
#pragma unroll
            for (int mi = 0; mi < 4; mi++) {
                int r = wm + mi * 16 + tr;
                af[mi][0] = As[cur][kb + tc    ][r    ];
                af[mi][1] = As[cur][kb + tc    ][r + 8];
                af[mi][2] = As[cur][kb + tc + 4][r    ];
                af[mi][3] = As[cur][kb + tc + 4][r + 8];
            }
#pragma unroll
            for (int ni = 0; ni < 8; ni++) {
                int c = wn + ni * 8 + tr;
                bf[ni][0] = Bs[cur][kb + tc    ][c];
                bf[ni][1] = Bs[cur][kb + tc + 4][c];
            }
#pragma unroll
            for (int mi = 0; mi < 4; mi++)
#pragma unroll
                for (int ni = 0; ni < 8; ni++)
                    mma8(acc[mi][ni], af[mi], bf[ni]);
        }
        if (kt + 1 < NK) {
            STS_TILE((kt + 1) & 1);
            __syncthreads();
        }
    }

#pragma unroll
    for (int mi = 0; mi < 4; mi++) {
        int r0 = wm + mi * 16 + tr;
        int r1 = r0 + 8;
#pragma unroll
        for (int ni = 0; ni < 8; ni++) {
            int c = nbase + wn + ni * 8 + tc * 2;
            if (r0 < rowsValid) {
                float2 v; v.x = acc[mi][ni][0]; v.y = acc[mi][ni][1];
                *(float2*)&Cbase[(size_t)(slot0 + r0) * CLD + c] = v;
            }
            if (r1 < rowsValid) {
                float2 v; v.x = acc[mi][ni][2]; v.y = acc[mi][ni][3];
                *(float2*)&Cbase[(size_t)(slot0 + r1) * CLD + c] = v;
            }
        }
    }
}
#undef LDG_TILE
#undef STS_TILE

// ---------------- silu-and-mul ----------------------------------------------
__global__ void silu_kernel() {
    const int per_row = I_DIM / 4;               // 352 float4 per row
    int idx = blockIdx.x * blockDim.x + threadIdx.x;
    if (idx >= S_SLOTS * per_row) return;
    int row = idx / per_row;
    int c4  = idx % per_row;
    const float4* gp = (const float4*)&g_gbuf[(size_t)row * TWOI];
    float4 g = gp[c4];
    float4 u = gp[c4 + per_row];
    float4 o;
    o.x = g.x / (1.f + expf(-g.x)) * u.x;
    o.y = g.y / (1.f + expf(-g.y)) * u.y;
    o.z = g.z / (1.f + expf(-g.z)) * u.z;
    o.w = g.w / (1.f + expf(-g.w)) * u.w;
    ((float4*)&g_actb[(size_t)row * I_DIM])[c4] = o;
}

// ---------------- weighted combine (exactly 2 slots per token) ---------------
__global__ void combine_kernel(float* __restrict__ out) {
    const int per_row = H_DIM / 4;               // 512 float4 per row
    int idx = blockIdx.x * blockDim.x + threadIdx.x;
    if (idx >= T_TOK * per_row) return;
    int t = idx / per_row;
    int h = idx % per_row;
    int p0 = g_slot[2*t], p1 = g_slot[2*t+1];
    float w0 = g_topw[2*t], w1 = g_topw[2*t+1];
    float4 y0 = ((const float4*)&g_ybuf[(size_t)p0 * H_DIM])[h];
    float4 y1 = ((const float4*)&g_ybuf[(size_t)p1 * H_DIM])[h];
    float4 o;
    o.x = w0 * y0.x + w1 * y1.x;
    o.y = w0 * y0.y + w1 * y1.y;
    o.z = w0 * y0.z + w1 * y1.z;
    o.w = w0 * y0.w + w1 * y1.w;
    ((float4*)out)[idx] = o;
}

// ---------------- launch -----------------------------------------------------
extern "C" void kernel_launch(void* const* d_in, const int* in_sizes, int n_in,
                              void* d_out, int out_size) {
    (void)in_sizes; (void)n_in; (void)out_size;
    const float* hidden = (const float*)d_in[0];
    const float* logits = (const float*)d_in[1];
    const float* w13    = (const float*)d_in[2];
    const float* w2     = (const float*)d_in[3];
    float* out = (float*)d_out;

    init_kernel<<<1, 32>>>();
    route_kernel<<<T_TOK / 256, 256>>>(logits);
    scan_kernel<<<1, 1>>>();
    perm_kernel<<<T_TOK / 256, 256>>>();

    // GEMM1: [M_e,2816] = gathered_hidden @ w13_e^T  (K=2048)
    moe_gemm<H_DIM, TWOI, TWOI, true>
        <<<dim3(TWOI / 128, T_TOK / 128, E_NUM), 128>>>(hidden, w13);

    int ns = S_SLOTS * (I_DIM / 4);
    silu_kernel<<<(ns + 255) / 256, 256>>>();

    // GEMM2: [M_e,2048] = act @ w2_e^T  (K=1408)
    moe_gemm<I_DIM, H_DIM, H_DIM, false>
        <<<dim3(H_DIM / 128, T_TOK / 128, E_NUM), 128>>>(nullptr, w2);

    int nc = T_TOK * (H_DIM / 4);
    combine_kernel<<<(nc + 255) / 256, 256>>>(out);
}

// round 7
// speedup vs baseline: 1.1980x; 1.1980x over previous
#include <cuda_runtime.h>
#include <math.h>
#include <stdint.h>

#define T_TOK 16384
#define H_DIM 2048
#define E_NUM 16
#define I_DIM 1408
#define TWOI  2816
#define S_SLOTS (T_TOK*2)

// ---------------- scratch (device globals: no allocations allowed) ----------
__device__ int   g_counts[E_NUM];
__device__ int   g_fill[E_NUM];
__device__ int   g_offs[E_NUM+1];
__device__ int   g_ids[S_SLOTS];
__device__ float g_topw[S_SLOTS];
__device__ int   g_perm[S_SLOTS];          // slot -> token
__device__ int   g_slot[S_SLOTS];          // (token,k) -> slot
__device__ float g_actb[(size_t)S_SLOTS * I_DIM];  // silu(g1)*g2 (GEMM1 epilogue)
__device__ float g_ybuf[(size_t)S_SLOTS * H_DIM];  // act @ w2^T

// ---------------- routing ---------------------------------------------------
__global__ void init_kernel() {
    int i = threadIdx.x;
    if (i < E_NUM) { g_counts[i] = 0; g_fill[i] = 0; }
}

__global__ void route_kernel(const float* __restrict__ logits) {
    int t = blockIdx.x * blockDim.x + threadIdx.x;
    if (t >= T_TOK) return;
    float l[E_NUM];
#pragma unroll
    for (int e = 0; e < E_NUM; e++) l[e] = logits[t * E_NUM + e];
    int e0 = 0; float m0 = l[0];
#pragma unroll
    for (int e = 1; e < E_NUM; e++) if (l[e] > m0) { m0 = l[e]; e0 = e; }
    int e1 = -1; float m1 = -1e30f;
#pragma unroll
    for (int e = 0; e < E_NUM; e++) if (e != e0 && l[e] > m1) { m1 = l[e]; e1 = e; }
    float w0 = 1.f / (1.f + expf(m1 - m0));   // renormalized top-2 softmax
    float w1 = 1.f - w0;
    g_ids[2*t] = e0;  g_ids[2*t+1] = e1;
    g_topw[2*t] = w0; g_topw[2*t+1] = w1;
    atomicAdd(&g_counts[e0], 1);
    atomicAdd(&g_counts[e1], 1);
}

__global__ void scan_kernel() {
    if (threadIdx.x == 0) {
        int acc = 0; g_offs[0] = 0;
        for (int e = 0; e < E_NUM; e++) { acc += g_counts[e]; g_offs[e+1] = acc; }
    }
}

__global__ void perm_kernel() {
    int t = blockIdx.x * blockDim.x + threadIdx.x;
    if (t >= T_TOK) return;
#pragma unroll
    for (int s = 0; s < 2; s++) {
        int e = g_ids[2*t+s];
        int pos = g_offs[e] + atomicAdd(&g_fill[e], 1);
        g_perm[pos] = t;
        g_slot[2*t+s] = pos;
    }
}

// ---------------- tf32 mma helpers ------------------------------------------
__device__ __forceinline__ uint32_t f2tf(float x) {
    uint32_t r; asm("cvt.rna.tf32.f32 %0, %1;" : "=r"(r) : "f"(x)); return r;
}
__device__ __forceinline__ void mma8(float* c, const uint32_t* a, const uint32_t* b) {
    asm volatile(
        "mma.sync.aligned.m16n8k8.row.col.f32.tf32.tf32.f32 "
        "{%0,%1,%2,%3},{%4,%5,%6,%7},{%8,%9},{%0,%1,%2,%3};"
        : "+f"(c[0]), "+f"(c[1]), "+f"(c[2]), "+f"(c[3])
        : "r"(a[0]), "r"(a[1]), "r"(a[2]), "r"(a[3]), "r"(b[0]), "r"(b[1]));
}

// ---------------- grouped GEMM: C[slot, n] = A[slot,:] . B_e[n,:] ------------
// CTA tile 128(M) x 256(N) x 16(K). 256 threads = 8 warps of 64x64 (2M x 4N).
// smem holds tf32-converted bits (cvt once at STS). Double buffered.
// G1: A = hidden[perm[slot]] (K=2048); B tile rows interleave gate/up:
//     smem B row 2j = w13[nb*128+j] (gate), row 2j+1 = w13[I+nb*128+j] (up).
//     => each thread's acc col-pair (even,odd) = (gate,up) of output col
//        nb*128 + wn/2 + ni*4 + tc  -> fused SiLU epilogue into g_actb.
// G2: A = g_actb (K=1408); B = w2[e] rows nb*256..+256 -> g_ybuf.
#define LDG_TILE(kt) {                                                   \
    const float4* ap_ = (const float4*)(arow + (kt)*16 + ahalf);         \
    ra0 = ap_[0]; ra1 = ap_[1];                                          \
    const float4* bp_ = (const float4*)(brow + (kt)*16);                 \
    rb0 = bp_[0]; rb1 = bp_[1]; rb2 = bp_[2]; rb3 = bp_[3]; }

#define STS_TILE(buf) {                                                  \
    uint32_t* as_ = &As[buf][ahalf][arr];                                \
    as_[0*136]=f2tf(ra0.x); as_[1*136]=f2tf(ra0.y);                      \
    as_[2*136]=f2tf(ra0.z); as_[3*136]=f2tf(ra0.w);                      \
    as_[4*136]=f2tf(ra1.x); as_[5*136]=f2tf(ra1.y);                      \
    as_[6*136]=f2tf(ra1.z); as_[7*136]=f2tf(ra1.w);                      \
    uint32_t* bs_ = &Bs[buf][0][tid];                                    \
    bs_[ 0*264]=f2tf(rb0.x); bs_[ 1*264]=f2tf(rb0.y);                    \
    bs_[ 2*264]=f2tf(rb0.z); bs_[ 3*264]=f2tf(rb0.w);                    \
    bs_[ 4*264]=f2tf(rb1.x); bs_[ 5*264]=f2tf(rb1.y);                    \
    bs_[ 6*264]=f2tf(rb1.z); bs_[ 7*264]=f2tf(rb1.w);                    \
    bs_[ 8*264]=f2tf(rb2.x); bs_[ 9*264]=f2tf(rb2.y);                    \
    bs_[10*264]=f2tf(rb2.z); bs_[11*264]=f2tf(rb2.w);                    \
    bs_[12*264]=f2tf(rb3.x); bs_[13*264]=f2tf(rb3.y);                    \
    bs_[14*264]=f2tf(rb3.z); bs_[15*264]=f2tf(rb3.w); }

#define GEMM_SMEM ((2*16*136 + 2*16*264) * 4)   // 51.2 KB dynamic

template<int KDIM, bool G1>
__global__ __launch_bounds__(256, 1) void moe_gemm(
    const float* __restrict__ Aext, const float* __restrict__ Bext)
{
    int e     = blockIdx.z;
    int off   = g_offs[e];
    int cnt   = g_offs[e+1] - off;
    int mbase = blockIdx.y * 128;
    if (mbase >= cnt) return;
    int rowsValid = cnt - mbase;                 // rows in this tile (<=128)
    int slot0 = off + mbase;
    int nb    = blockIdx.x;

    extern __shared__ uint32_t dynsm[];
    uint32_t (*As)[16][136] = (uint32_t(*)[16][136])dynsm;          // [buf][k][m]
    uint32_t (*Bs)[16][264] = (uint32_t(*)[16][264])(dynsm + 2*16*136);

    int tid   = threadIdx.x;
    int arr   = tid >> 1;                        // A row 0..127
    int ahalf = (tid & 1) * 8;                   // k-half 0/8

    // A source row
    int slot = slot0 + arr;
    if (slot >= S_SLOTS) slot = S_SLOTS - 1;     // clamp; output masked
    const float* arow = G1 ? (Aext + (size_t)g_perm[slot] * KDIM)
                           : (g_actb + (size_t)slot * KDIM);
    // B source row (one per thread, 256 rows)
    const float* brow;
    if (G1) {
        int jl   = tid >> 1;                     // 0..127 output col within block
        int type = tid & 1;                      // 0=gate, 1=up
        int grow = nb * 128 + jl + type * I_DIM;
        brow = Bext + (size_t)e * TWOI * H_DIM + (size_t)grow * H_DIM;
    } else {
        brow = Bext + (size_t)e * H_DIM * I_DIM + (size_t)(nb * 256 + tid) * I_DIM;
    }

    int lane = tid & 31;
    int warp = tid >> 5;
    int wm = (warp & 1) * 64;                    // 2(M) x 4(N) warp grid
    int wn = (warp >> 1) * 64;
    int tr = lane >> 2;                          // 0..7
    int tc = lane & 3;                           // 0..3

    float acc[4][8][4];
#pragma unroll
    for (int a = 0; a < 4; a++)
#pragma unroll
        for (int b = 0; b < 8; b++)
#pragma unroll
            for (int c = 0; c < 4; c++) acc[a][b][c] = 0.f;

    float4 ra0, ra1, rb0, rb1, rb2, rb3;
    constexpr int NK = KDIM / 16;

    LDG_TILE(0);
    STS_TILE(0);
    __syncthreads();

#pragma unroll 1
    for (int kt = 0; kt < NK; kt++) {
        int cur = kt & 1;
        if (kt + 1 < NK) LDG_TILE(kt + 1);       // global prefetch over compute
#pragma unroll
        for (int ks = 0; ks < 2; ks++) {
            int kb = ks * 8;
            uint32_t af[4][4], bf[8][2];
#pragma unroll
            for (int mi = 0; mi < 4; mi++) {
                int r = wm + mi * 16 + tr;
                af[mi][0] = As[cur][kb + tc    ][r    ];
                af[mi][1] = As[cur][kb + tc    ][r + 8];
                af[mi][2] = As[cur][kb + tc + 4][r    ];
                af[mi][3] = As[cur][kb + tc + 4][r + 8];
            }
#pragma unroll
            for (int ni = 0; ni < 8; ni++) {
                int c = wn + ni * 8 + tr;
                bf[ni][0] = Bs[cur][kb + tc    ][c];
                bf[ni][1] = Bs[cur][kb + tc + 4][c];
            }
#pragma unroll
            for (int mi = 0; mi < 4; mi++)
#pragma unroll
                for (int ni = 0; ni < 8; ni++)
                    mma8(acc[mi][ni], af[mi], bf[ni]);
        }
        if (kt + 1 < NK) {
            STS_TILE((kt + 1) & 1);
            __syncthreads();
        }
    }

    // ---- epilogue -----------------------------------------------------------
    if (G1) {
        // acc cols: even = gate(j), odd = up(j); j = wn/2 + ni*4 + tc
#pragma unroll
        for (int mi = 0; mi < 4; mi++) {
            int r0 = wm + mi * 16 + tr;
            int r1 = r0 + 8;
#pragma unroll
            for (int ni = 0; ni < 8; ni++) {
                int col = nb * 128 + (wn >> 1) + ni * 4 + tc;
                if (r0 < rowsValid) {
                    float g = acc[mi][ni][0], u = acc[mi][ni][1];
                    g_actb[(size_t)(slot0 + r0) * I_DIM + col] =
                        g / (1.f + __expf(-g)) * u;
                }
                if (r1 < rowsValid) {
                    float g = acc[mi][ni][2], u = acc[mi][ni][3];
                    g_actb[(size_t)(slot0 + r1) * I_DIM + col] =
                        g / (1.f + __expf(-g)) * u;
                }
            }
        }
    } else {
#pragma unroll
        for (int mi = 0; mi < 4; mi++) {
            int r0 = wm + mi * 16 + tr;
            int r1 = r0 + 8;
#pragma unroll
            for (int ni = 0; ni < 8; ni++) {
                int c = nb * 256 + wn + ni * 8 + tc * 2;
                if (r0 < rowsValid) {
                    float2 v; v.x = acc[mi][ni][0]; v.y = acc[mi][ni][1];
                    *(float2*)&g_ybuf[(size_t)(slot0 + r0) * H_DIM + c] = v;
                }
                if (r1 < rowsValid) {
                    float2 v; v.x = acc[mi][ni][2]; v.y = acc[mi][ni][3];
                    *(float2*)&g_ybuf[(size_t)(slot0 + r1) * H_DIM + c] = v;
                }
            }
        }
    }
}
#undef LDG_TILE
#undef STS_TILE

// ---------------- weighted combine (exactly 2 slots per token) ---------------
__global__ void combine_kernel(float* __restrict__ out) {
    const int per_row = H_DIM / 4;
    int idx = blockIdx.x * blockDim.x + threadIdx.x;
    if (idx >= T_TOK * per_row) return;
    int t = idx / per_row;
    int h = idx % per_row;
    int p0 = g_slot[2*t], p1 = g_slot[2*t+1];
    float w0 = g_topw[2*t], w1 = g_topw[2*t+1];
    float4 y0 = ((const float4*)&g_ybuf[(size_t)p0 * H_DIM])[h];
    float4 y1 = ((const float4*)&g_ybuf[(size_t)p1 * H_DIM])[h];
    float4 o;
    o.x = w0 * y0.x + w1 * y1.x;
    o.y = w0 * y0.y + w1 * y1.y;
    o.z = w0 * y0.z + w1 * y1.z;
    o.w = w0 * y0.w + w1 * y1.w;
    ((float4*)out)[idx] = o;
}

// ---------------- launch -----------------------------------------------------
extern "C" void kernel_launch(void* const* d_in, const int* in_sizes, int n_in,
                              void* d_out, int out_size) {
    (void)in_sizes; (void)n_in; (void)out_size;
    const float* hidden = (const float*)d_in[0];
    const float* logits = (const float*)d_in[1];
    const float* w13    = (const float*)d_in[2];
    const float* w2     = (const float*)d_in[3];
    float* out = (float*)d_out;

    cudaFuncSetAttribute(moe_gemm<H_DIM, true>,
                         cudaFuncAttributeMaxDynamicSharedMemorySize, GEMM_SMEM);
    cudaFuncSetAttribute(moe_gemm<I_DIM, false>,
                         cudaFuncAttributeMaxDynamicSharedMemorySize, GEMM_SMEM);

    init_kernel<<<1, 32>>>();
    route_kernel<<<T_TOK / 256, 256>>>(logits);
    scan_kernel<<<1, 1>>>();
    perm_kernel<<<T_TOK / 256, 256>>>();

    // GEMM1 + fused SiLU: act[slot, 1408]; N-block = 128 output cols
    moe_gemm<H_DIM, true>
        <<<dim3(I_DIM / 128, S_SLOTS / 128, E_NUM), 256, GEMM_SMEM>>>(hidden, w13);

    // GEMM2: y[slot, 2048] = act @ w2_e^T; N-block = 256 cols
    moe_gemm<I_DIM, false>
        <<<dim3(H_DIM / 256, S_SLOTS / 128, E_NUM), 256, GEMM_SMEM>>>(nullptr, w2);

    int nc = T_TOK * (H_DIM / 4);
    combine_kernel<<<(nc + 255) / 256, 256>>>(out);
}

// round 8
// speedup vs baseline: 2.1237x; 1.7728x over previous
#include <cuda_runtime.h>
#include <cuda_fp16.h>
#include <math.h>
#include <stdint.h>

#define T_TOK 16384
#define H_DIM 2048
#define E_NUM 16
#define I_DIM 1408
#define TWOI  2816
#define S_SLOTS (T_TOK*2)

// ---------------- scratch (device globals: no allocations allowed) ----------
__device__ int    g_counts[E_NUM];
__device__ int    g_fill[E_NUM];
__device__ int    g_offs[E_NUM+1];
__device__ int    g_ids[S_SLOTS];
__device__ float  g_topw[S_SLOTS];
__device__ int    g_perm[S_SLOTS];         // slot -> token
__device__ int    g_slot[S_SLOTS];         // (token,k) -> slot
__device__ __half g_xh [(size_t)T_TOK * H_DIM];         // fp16 hidden
__device__ __half g_w13h[(size_t)E_NUM * TWOI * H_DIM]; // fp16 w13
__device__ __half g_w2h [(size_t)E_NUM * H_DIM * I_DIM];// fp16 w2
__device__ __half g_acth[(size_t)S_SLOTS * I_DIM];      // fp16 silu(g)*u
__device__ float  g_ybuf[(size_t)S_SLOTS * H_DIM];      // fp32 act @ w2^T

// ---------------- routing ---------------------------------------------------
__global__ void init_kernel() {
    int i = threadIdx.x;
    if (i < E_NUM) { g_counts[i] = 0; g_fill[i] = 0; }
}

__global__ void route_kernel(const float* __restrict__ logits) {
    int t = blockIdx.x * blockDim.x + threadIdx.x;
    if (t >= T_TOK) return;
    float l[E_NUM];
#pragma unroll
    for (int e = 0; e < E_NUM; e++) l[e] = logits[t * E_NUM + e];
    int e0 = 0; float m0 = l[0];
#pragma unroll
    for (int e = 1; e < E_NUM; e++) if (l[e] > m0) { m0 = l[e]; e0 = e; }
    int e1 = -1; float m1 = -1e30f;
#pragma unroll
    for (int e = 0; e < E_NUM; e++) if (e != e0 && l[e] > m1) { m1 = l[e]; e1 = e; }
    float w0 = 1.f / (1.f + expf(m1 - m0));   // renormalized top-2 softmax
    float w1 = 1.f - w0;
    g_ids[2*t] = e0;  g_ids[2*t+1] = e1;
    g_topw[2*t] = w0; g_topw[2*t+1] = w1;
    atomicAdd(&g_counts[e0], 1);
    atomicAdd(&g_counts[e1], 1);
}

__global__ void scan_kernel() {
    if (threadIdx.x == 0) {
        int acc = 0; g_offs[0] = 0;
        for (int e = 0; e < E_NUM; e++) { acc += g_counts[e]; g_offs[e+1] = acc; }
    }
}

__global__ void perm_kernel() {
    int t = blockIdx.x * blockDim.x + threadIdx.x;
    if (t >= T_TOK) return;
#pragma unroll
    for (int s = 0; s < 2; s++) {
        int e = g_ids[2*t+s];
        int pos = g_offs[e] + atomicAdd(&g_fill[e], 1);
        g_perm[pos] = t;
        g_slot[2*t+s] = pos;
    }
}

// ---------------- fp32 -> fp16 bulk convert (8 elems/thread) -----------------
__global__ void cvt_f2h(const float* __restrict__ s, __half* __restrict__ d, int n8) {
    int i = blockIdx.x * blockDim.x + threadIdx.x;
    if (i >= n8) return;
    const float4* sp = (const float4*)s + (size_t)i * 2;
    float4 a = sp[0], b = sp[1];
    __half2 h0 = __floats2half2_rn(a.x, a.y);
    __half2 h1 = __floats2half2_rn(a.z, a.w);
    __half2 h2 = __floats2half2_rn(b.x, b.y);
    __half2 h3 = __floats2half2_rn(b.z, b.w);
    uint4 o;
    o.x = *(uint32_t*)&h0; o.y = *(uint32_t*)&h1;
    o.z = *(uint32_t*)&h2; o.w = *(uint32_t*)&h3;
    ((uint4*)d)[i] = o;
}

// ---------------- mma helpers ------------------------------------------------
__device__ __forceinline__ void mma16(float* c, const uint32_t* a, const uint32_t* b) {
    asm volatile(
        "mma.sync.aligned.m16n8k16.row.col.f32.f16.f16.f32 "
        "{%0,%1,%2,%3},{%4,%5,%6,%7},{%8,%9},{%0,%1,%2,%3};"
        : "+f"(c[0]), "+f"(c[1]), "+f"(c[2]), "+f"(c[3])
        : "r"(a[0]), "r"(a[1]), "r"(a[2]), "r"(a[3]), "r"(b[0]), "r"(b[1]));
}
__device__ __forceinline__ void cpa16(uint32_t dst, const void* src) {
    asm volatile("cp.async.cg.shared.global [%0], [%1], 16;\n" :: "r"(dst), "l"(src));
}
__device__ __forceinline__ uint32_t smem_u32(const void* p) {
    uint32_t a;
    asm("{ .reg .u64 t; cvta.to.shared.u64 t, %1; cvt.u32.u64 %0, t; }"
        : "=r"(a) : "l"(p));
    return a;
}

// ---------------- grouped fp16 GEMM ------------------------------------------
// CTA tile 128(M) x 256(N) x 32(K-halves). 256 threads = 8 warps of 64x64.
// 3-stage cp.async pipeline, smem [row][k] half2, row stride 80B (20 words,
// conflict-free fragment LDS). All operands fp16 in gmem -> pure cp.async fill.
// G1: A = g_xh[perm[slot]] (K=2048); B rows interleave gate/up of w13 so each
//     thread's C col-pair = (gate, up) of one output col -> fused SiLU into
//     g_acth. G2: A = g_acth (K=1408); B = w2 rows -> g_ybuf fp32.
#define A_BYTES 10240               // 128 rows * 80B
#define B_BYTES 20480               // 256 rows * 80B
#define STAGE_BYTES (A_BYTES + B_BYTES)
#define GEMM_SMEM (3 * STAGE_BYTES) // 92160

template<int KDIM, bool G1>
__global__ __launch_bounds__(256, 1) void moe_gemm(void)
{
    constexpr int NK = KDIM / 32;             // 32 halves (64B) per k-block
    int e     = blockIdx.z;
    int off   = g_offs[e];
    int cnt   = g_offs[e+1] - off;
    int mbase = blockIdx.y * 128;
    if (mbase >= cnt) return;
    int rowsValid = cnt - mbase;
    int slot0 = off + mbase;
    int nb    = blockIdx.x;

    extern __shared__ char dynsm[];
    uint32_t smbase = smem_u32(dynsm);

    int tid  = threadIdx.x;
    int lane = tid & 31;
    int warp = tid >> 5;

    // A source row (2 threads per row, 32B halves each)
    int arr = tid >> 1, ah = tid & 1;
    int slot = slot0 + arr;
    if (slot >= S_SLOTS) slot = S_SLOTS - 1;  // clamp; output masked
    const char* arow;
    if (G1) arow = (const char*)(g_xh + (size_t)g_perm[slot] * KDIM);
    else    arow = (const char*)(g_acth + (size_t)slot * KDIM);
    // B source row (1 thread per row)
    const char* brow;
    if (G1) {
        int jl   = tid >> 1;                  // output col within 128-block
        int type = tid & 1;                   // 0=gate, 1=up
        int grow = nb * 128 + jl + type * I_DIM;
        brow = (const char*)(g_w13h + (size_t)e * TWOI * H_DIM
                                     + (size_t)grow * H_DIM);
    } else {
        brow = (const char*)(g_w2h + (size_t)e * H_DIM * I_DIM
                                    + (size_t)(nb * 256 + tid) * I_DIM);
    }
    uint32_t aoff = (uint32_t)arr * 80 + (uint32_t)ah * 32;
    uint32_t boff = (uint32_t)tid * 80;

#define FILL(kt) {                                                       \
    uint32_t sa_ = smbase + ((kt) % 3) * STAGE_BYTES;                    \
    uint32_t sb_ = sa_ + A_BYTES;                                        \
    const char* ap_ = arow + (size_t)(kt) * 64 + ah * 32;                \
    cpa16(sa_ + aoff,      ap_);                                         \
    cpa16(sa_ + aoff + 16, ap_ + 16);                                    \
    const char* bp_ = brow + (size_t)(kt) * 64;                          \
    cpa16(sb_ + boff,      bp_);                                         \
    cpa16(sb_ + boff + 16, bp_ + 16);                                    \
    cpa16(sb_ + boff + 32, bp_ + 32);                                    \
    cpa16(sb_ + boff + 48, bp_ + 48);                                    \
    asm volatile("cp.async.commit_group;\n" ::: "memory"); }

    int wm = (warp & 1) * 64;                 // 2(M) x 4(N) warp grid, 64x64
    int wn = (warp >> 1) * 64;
    int tr = lane >> 2;                       // 0..7
    int tc = lane & 3;                        // 0..3

    float acc[4][8][4];
#pragma unroll
    for (int a = 0; a < 4; a++)
#pragma unroll
        for (int b = 0; b < 8; b++)
#pragma unroll
            for (int c = 0; c < 4; c++) acc[a][b][c] = 0.f;

    FILL(0);
    FILL(1);

#pragma unroll 1
    for (int kt = 0; kt < NK; kt++) {
        if (kt + 1 < NK) asm volatile("cp.async.wait_group 1;\n" ::: "memory");
        else             asm volatile("cp.async.wait_group 0;\n" ::: "memory");
        __syncthreads();
        if (kt + 2 < NK) FILL(kt + 2);

        const uint32_t* Asw = (const uint32_t*)(dynsm + (kt % 3) * STAGE_BYTES);
        const uint32_t* Bsw = Asw + A_BYTES / 4;
#pragma unroll
        for (int ks = 0; ks < 2; ks++) {
            int ko = ks * 8;                  // half2 col offset within row
            uint32_t af[4][4], bf[8][2];
#pragma unroll
            for (int mi = 0; mi < 4; mi++) {
                int r = wm + mi * 16 + tr;
                af[mi][0] = Asw[(r    ) * 20 + ko + tc    ];
                af[mi][1] = Asw[(r + 8) * 20 + ko + tc    ];
                af[mi][2] = Asw[(r    ) * 20 + ko + tc + 4];
                af[mi][3] = Asw[(r + 8) * 20 + ko + tc + 4];
            }
#pragma unroll
            for (int ni = 0; ni < 8; ni++) {
                int n = wn + ni * 8 + tr;
                bf[ni][0] = Bsw[n * 20 + ko + tc    ];
                bf[ni][1] = Bsw[n * 20 + ko + tc + 4];
            }
#pragma unroll
            for (int mi = 0; mi < 4; mi++)
#pragma unroll
                for (int ni = 0; ni < 8; ni++)
                    mma16(acc[mi][ni], af[mi], bf[ni]);
        }
    }
#undef FILL

    // ---- epilogue -----------------------------------------------------------
    if (G1) {
        // C col-pair (2tc, 2tc+1) = (gate, up) of output col j
#pragma unroll
        for (int mi = 0; mi < 4; mi++) {
            int r0 = wm + mi * 16 + tr;
            int r1 = r0 + 8;
#pragma unroll
            for (int ni = 0; ni < 8; ni++) {
                int col = nb * 128 + (wn >> 1) + ni * 4 + tc;
                if (r0 < rowsValid) {
                    float g = acc[mi][ni][0], u = acc[mi][ni][1];
                    g_acth[(size_t)(slot0 + r0) * I_DIM + col] =
                        __float2half_rn(g / (1.f + __expf(-g)) * u);
                }
                if (r1 < rowsValid) {
                    float g = acc[mi][ni][2], u = acc[mi][ni][3];
                    g_acth[(size_t)(slot0 + r1) * I_DIM + col] =
                        __float2half_rn(g / (1.f + __expf(-g)) * u);
                }
            }
        }
    } else {
#pragma unroll
        for (int mi = 0; mi < 4; mi++) {
            int r0 = wm + mi * 16 + tr;
            int r1 = r0 + 8;
#pragma unroll
            for (int ni = 0; ni < 8; ni++) {
                int c = nb * 256 + wn + ni * 8 + tc * 2;
                if (r0 < rowsValid) {
                    float2 v; v.x = acc[mi][ni][0]; v.y = acc[mi][ni][1];
                    *(float2*)&g_ybuf[(size_t)(slot0 + r0) * H_DIM + c] = v;
                }
                if (r1 < rowsValid) {
                    float2 v; v.x = acc[mi][ni][2]; v.y = acc[mi][ni][3];
                    *(float2*)&g_ybuf[(size_t)(slot0 + r1) * H_DIM + c] = v;
                }
            }
        }
    }
}

// ---------------- weighted combine (exactly 2 slots per token) ---------------
__global__ void combine_kernel(float* __restrict__ out) {
    const int per_row = H_DIM / 4;
    int idx = blockIdx.x * blockDim.x + threadIdx.x;
    if (idx >= T_TOK * per_row) return;
    int t = idx / per_row;
    int h = idx % per_row;
    int p0 = g_slot[2*t], p1 = g_slot[2*t+1];
    float w0 = g_topw[2*t], w1 = g_topw[2*t+1];
    float4 y0 = ((const float4*)&g_ybuf[(size_t)p0 * H_DIM])[h];
    float4 y1 = ((const float4*)&g_ybuf[(size_t)p1 * H_DIM])[h];
    float4 o;
    o.x = w0 * y0.x + w1 * y1.x;
    o.y = w0 * y0.y + w1 * y1.y;
    o.z = w0 * y0.z + w1 * y1.z;
    o.w = w0 * y0.w + w1 * y1.w;
    ((float4*)out)[idx] = o;
}

// ---------------- launch -----------------------------------------------------
extern "C" void kernel_launch(void* const* d_in, const int* in_sizes, int n_in,
                              void* d_out, int out_size) {
    (void)in_sizes; (void)n_in; (void)out_size;
    const float* hidden = (const float*)d_in[0];
    const float* logits = (const float*)d_in[1];
    const float* w13    = (const float*)d_in[2];
    const float* w2     = (const float*)d_in[3];
    float* out = (float*)d_out;

    cudaFuncSetAttribute(moe_gemm<H_DIM, true>,
                         cudaFuncAttributeMaxDynamicSharedMemorySize, GEMM_SMEM);
    cudaFuncSetAttribute(moe_gemm<I_DIM, false>,
                         cudaFuncAttributeMaxDynamicSharedMemorySize, GEMM_SMEM);

    init_kernel<<<1, 32>>>();
    route_kernel<<<T_TOK / 256, 256>>>(logits);
    scan_kernel<<<1, 1>>>();
    perm_kernel<<<T_TOK / 256, 256>>>();

    // fp32 -> fp16 operand conversion (device-global staging)
    {
        __half* dxh;  cudaGetSymbolAddress((void**)&dxh,  g_xh);
        __half* dw13; cudaGetSymbolAddress((void**)&dw13, g_w13h);
        __half* dw2;  cudaGetSymbolAddress((void**)&dw2,  g_w2h);
        int n8x  = T_TOK * H_DIM / 8;
        int n8w1 = E_NUM * TWOI * H_DIM / 8;
        int n8w2 = E_NUM * H_DIM * I_DIM / 8;
        cvt_f2h<<<(n8x  + 255) / 256, 256>>>(hidden, dxh,  n8x);
        cvt_f2h<<<(n8w1 + 255) / 256, 256>>>(w13,    dw13, n8w1);
        cvt_f2h<<<(n8w2 + 255) / 256, 256>>>(w2,     dw2,  n8w2);
    }

    // GEMM1 + fused SiLU: g_acth[slot, 1408]
    moe_gemm<H_DIM, true>
        <<<dim3(I_DIM / 128, S_SLOTS / 128, E_NUM), 256, GEMM_SMEM>>>();

    // GEMM2: g_ybuf[slot, 2048] = act @ w2_e^T
    moe_gemm<I_DIM, false>
        <<<dim3(H_DIM / 256, S_SLOTS / 128, E_NUM), 256, GEMM_SMEM>>>();

    int nc = T_TOK * (H_DIM / 4);
    combine_kernel<<<(nc + 255) / 256, 256>>>(out);
}

// round 9
// speedup vs baseline: 2.2080x; 1.0397x over previous
#include <cuda_runtime.h>
#include <cuda_fp16.h>
#include <math.h>
#include <stdint.h>

#define T_TOK 16384
#define H_DIM 2048
#define E_NUM 16
#define I_DIM 1408
#define TWOI  2816
#define S_SLOTS (T_TOK*2)

// ---------------- scratch (device globals: no allocations allowed) ----------
__device__ int    g_counts[E_NUM];
__device__ int    g_fill[E_NUM];
__device__ int    g_offs[E_NUM+1];
__device__ int    g_ids[S_SLOTS];
__device__ float  g_topw[S_SLOTS];
__device__ int    g_perm[S_SLOTS];         // slot -> token
__device__ int    g_slot[S_SLOTS];         // (token,k) -> slot
__device__ __half g_xh [(size_t)T_TOK * H_DIM];         // fp16 hidden
__device__ __half g_w13h[(size_t)E_NUM * TWOI * H_DIM]; // fp16 w13
__device__ __half g_w2h [(size_t)E_NUM * H_DIM * I_DIM];// fp16 w2
__device__ __half g_acth[(size_t)S_SLOTS * I_DIM];      // fp16 silu(g)*u
__device__ __half g_yh  [(size_t)S_SLOTS * H_DIM];      // fp16 act @ w2^T

// ---------------- routing ---------------------------------------------------
__global__ void init_kernel() {
    int i = threadIdx.x;
    if (i < E_NUM) { g_counts[i] = 0; g_fill[i] = 0; }
}

__global__ void route_kernel(const float* __restrict__ logits) {
    int t = blockIdx.x * blockDim.x + threadIdx.x;
    if (t >= T_TOK) return;
    float l[E_NUM];
#pragma unroll
    for (int e = 0; e < E_NUM; e++) l[e] = logits[t * E_NUM + e];
    int e0 = 0; float m0 = l[0];
#pragma unroll
    for (int e = 1; e < E_NUM; e++) if (l[e] > m0) { m0 = l[e]; e0 = e; }
    int e1 = -1; float m1 = -1e30f;
#pragma unroll
    for (int e = 0; e < E_NUM; e++) if (e != e0 && l[e] > m1) { m1 = l[e]; e1 = e; }
    float w0 = 1.f / (1.f + expf(m1 - m0));   // renormalized top-2 softmax
    float w1 = 1.f - w0;
    g_ids[2*t] = e0;  g_ids[2*t+1] = e1;
    g_topw[2*t] = w0; g_topw[2*t+1] = w1;
    atomicAdd(&g_counts[e0], 1);
    atomicAdd(&g_counts[e1], 1);
}

__global__ void scan_kernel() {
    if (threadIdx.x == 0) {
        int acc = 0; g_offs[0] = 0;
        for (int e = 0; e < E_NUM; e++) { acc += g_counts[e]; g_offs[e+1] = acc; }
    }
}

__global__ void perm_kernel() {
    int t = blockIdx.x * blockDim.x + threadIdx.x;
    if (t >= T_TOK) return;
#pragma unroll
    for (int s = 0; s < 2; s++) {
        int e = g_ids[2*t+s];
        int pos = g_offs[e] + atomicAdd(&g_fill[e], 1);
        g_perm[pos] = t;
        g_slot[2*t+s] = pos;
    }
}

// ---------------- fp32 -> fp16 bulk convert (8 elems/thread) -----------------
__global__ void cvt_f2h(const float* __restrict__ s, __half* __restrict__ d, int n8) {
    int i = blockIdx.x * blockDim.x + threadIdx.x;
    if (i >= n8) return;
    const float4* sp = (const float4*)s + (size_t)i * 2;
    float4 a = sp[0], b = sp[1];
    __half2 h0 = __floats2half2_rn(a.x, a.y);
    __half2 h1 = __floats2half2_rn(a.z, a.w);
    __half2 h2 = __floats2half2_rn(b.x, b.y);
    __half2 h3 = __floats2half2_rn(b.z, b.w);
    uint4 o;
    o.x = *(uint32_t*)&h0; o.y = *(uint32_t*)&h1;
    o.z = *(uint32_t*)&h2; o.w = *(uint32_t*)&h3;
    ((uint4*)d)[i] = o;
}

// ---------------- mma helpers ------------------------------------------------
__device__ __forceinline__ void mma16(float* c, const uint32_t* a, const uint32_t* b) {
    asm volatile(
        "mma.sync.aligned.m16n8k16.row.col.f32.f16.f16.f32 "
        "{%0,%1,%2,%3},{%4,%5,%6,%7},{%8,%9},{%0,%1,%2,%3};"
        : "+f"(c[0]), "+f"(c[1]), "+f"(c[2]), "+f"(c[3])
        : "r"(a[0]), "r"(a[1]), "r"(a[2]), "r"(a[3]), "r"(b[0]), "r"(b[1]));
}
__device__ __forceinline__ void cpa16(uint32_t dst, const void* src) {
    asm volatile("cp.async.cg.shared.global [%0], [%1], 16;\n" :: "r"(dst), "l"(src));
}
__device__ __forceinline__ uint32_t smem_u32(const void* p) {
    uint32_t a;
    asm("{ .reg .u64 t; cvta.to.shared.u64 t, %1; cvt.u32.u64 %0, t; }"
        : "=r"(a) : "l"(p));
    return a;
}

// ---------------- grouped fp16 GEMM ------------------------------------------
// CTA tile 128(M) x 256(N) x 64(K-halves per stage). 256 threads, 8 warps of
// 64x64. Stage = two 32-K sub-blocks (one cp.async group + one __syncthreads
// per 64-K stage). Fragments double-buffered: LDS for ks+1 issued before the
// MMAs of ks, hiding fragment latency under tensor work. smem rows 80B
// (64B data + 16B pad), conflict-free for the fragment access pattern.
// G1: A = g_xh[perm[slot]] (K=2048); B rows interleave gate/up of w13 so each
//     thread's C col-pair = (gate, up) of one output col -> fused SiLU into
//     g_acth. G2: A = g_acth (K=1408); B = w2 rows -> g_yh (fp16).
#define A_BYTES 10240               // 128 rows * 80B
#define B_BYTES 20480               // 256 rows * 80B
#define SUB_BYTES (A_BYTES + B_BYTES)        // 30720 (one 32-K sub-block)
#define STAGE_BYTES (2 * SUB_BYTES)          // 61440 (64-K stage)
#define GEMM_SMEM (3 * STAGE_BYTES)          // 184320

template<int KDIM, bool G1>
__global__ __launch_bounds__(256, 1) void moe_gemm(void)
{
    constexpr int NK = KDIM / 64;             // 64-half (128B) stages
    int e     = blockIdx.z;
    int off   = g_offs[e];
    int cnt   = g_offs[e+1] - off;
    int mbase = blockIdx.y * 128;
    if (mbase >= cnt) return;
    int rowsValid = cnt - mbase;
    int slot0 = off + mbase;
    int nb    = blockIdx.x;

    extern __shared__ char dynsm[];
    uint32_t smbase = smem_u32(dynsm);

    int tid  = threadIdx.x;
    int lane = tid & 31;
    int warp = tid >> 5;

    // A source row (2 threads per row, 32B halves of each 64B sub-row)
    int arr = tid >> 1, ah = tid & 1;
    int slot = slot0 + arr;
    if (slot >= S_SLOTS) slot = S_SLOTS - 1;  // clamp; output masked
    const char* arow;
    if (G1) arow = (const char*)(g_xh + (size_t)g_perm[slot] * KDIM);
    else    arow = (const char*)(g_acth + (size_t)slot * KDIM);
    // B source row (1 thread per row)
    const char* brow;
    if (G1) {
        int jl   = tid >> 1;                  // output col within 128-block
        int type = tid & 1;                   // 0=gate, 1=up
        int grow = nb * 128 + jl + type * I_DIM;
        brow = (const char*)(g_w13h + (size_t)e * TWOI * H_DIM
                                     + (size_t)grow * H_DIM);
    } else {
        brow = (const char*)(g_w2h + (size_t)e * H_DIM * I_DIM
                                    + (size_t)(nb * 256 + tid) * I_DIM);
    }
    uint32_t aoff = (uint32_t)arr * 80 + (uint32_t)ah * 32;
    uint32_t boff = (uint32_t)tid * 80;

    // fill one 64-K stage (two sub-blocks), single commit
#define FILL(kt) {                                                       \
    uint32_t st_ = smbase + ((kt) % 3) * STAGE_BYTES;                    \
    const char* ap_ = arow + (size_t)(kt) * 128 + ah * 32;               \
    const char* bp_ = brow + (size_t)(kt) * 128;                         \
    _Pragma("unroll")                                                    \
    for (int j_ = 0; j_ < 2; j_++) {                                     \
        uint32_t sa_ = st_ + j_ * SUB_BYTES;                             \
        uint32_t sb_ = sa_ + A_BYTES;                                    \
        cpa16(sa_ + aoff,      ap_ + j_ * 64);                           \
        cpa16(sa_ + aoff + 16, ap_ + j_ * 64 + 16);                      \
        cpa16(sb_ + boff,      bp_ + j_ * 64);                           \
        cpa16(sb_ + boff + 16, bp_ + j_ * 64 + 16);                      \
        cpa16(sb_ + boff + 32, bp_ + j_ * 64 + 32);                      \
        cpa16(sb_ + boff + 48, bp_ + j_ * 64 + 48);                      \
    }                                                                    \
    asm volatile("cp.async.commit_group;\n" ::: "memory"); }

    int wm = (warp & 1) * 64;                 // 2(M) x 4(N) warp grid, 64x64
    int wn = (warp >> 1) * 64;
    int tr = lane >> 2;                       // 0..7
    int tc = lane & 3;                        // 0..3

    float acc[4][8][4];
#pragma unroll
    for (int a = 0; a < 4; a++)
#pragma unroll
        for (int b = 0; b < 8; b++)
#pragma unroll
            for (int c = 0; c < 4; c++) acc[a][b][c] = 0.f;

    // fragment load for sub-phase ks (0..3) of the stage at stp, into buf p
    uint32_t af[2][4][4], bf[2][8][2];
#define LOADF(p, stp, ks) {                                              \
    const uint32_t* Asw_ = (const uint32_t*)((stp) + ((ks) >> 1) * SUB_BYTES); \
    const uint32_t* Bsw_ = (const uint32_t*)((stp) + ((ks) >> 1) * SUB_BYTES + A_BYTES); \
    int ko_ = ((ks) & 1) * 8;                                            \
    _Pragma("unroll")                                                    \
    for (int mi_ = 0; mi_ < 4; mi_++) {                                  \
        int r_ = wm + mi_ * 16 + tr;                                     \
        af[p][mi_][0] = Asw_[(r_    ) * 20 + ko_ + tc    ];              \
        af[p][mi_][1] = Asw_[(r_ + 8) * 20 + ko_ + tc    ];              \
        af[p][mi_][2] = Asw_[(r_    ) * 20 + ko_ + tc + 4];              \
        af[p][mi_][3] = Asw_[(r_ + 8) * 20 + ko_ + tc + 4];              \
    }                                                                    \
    _Pragma("unroll")                                                    \
    for (int ni_ = 0; ni_ < 8; ni_++) {                                  \
        int n_ = wn + ni_ * 8 + tr;                                      \
        bf[p][ni_][0] = Bsw_[n_ * 20 + ko_ + tc    ];                    \
        bf[p][ni_][1] = Bsw_[n_ * 20 + ko_ + tc + 4];                    \
    }                                                                    \
}
#define MMAS(p) {                                                        \
    _Pragma("unroll")                                                    \
    for (int mi_ = 0; mi_ < 4; mi_++)                                    \
        _Pragma("unroll")                                                \
        for (int ni_ = 0; ni_ < 8; ni_++)                                \
            mma16(acc[mi_][ni_], af[p][mi_], bf[p][ni_]);                \
}

    FILL(0);
    FILL(1);

#pragma unroll 1
    for (int kt = 0; kt < NK; kt++) {
        if (kt + 1 < NK) asm volatile("cp.async.wait_group 1;\n" ::: "memory");
        else             asm volatile("cp.async.wait_group 0;\n" ::: "memory");
        __syncthreads();
        if (kt + 2 < NK) FILL(kt + 2);

        const char* stp = dynsm + (kt % 3) * STAGE_BYTES;
        LOADF(0, stp, 0);
        LOADF(1, stp, 1);  MMAS(0);
        LOADF(0, stp, 2);  MMAS(1);
        LOADF(1, stp, 3);  MMAS(0);
        MMAS(1);
    }
#undef FILL
#undef LOADF
#undef MMAS

    // ---- epilogue -----------------------------------------------------------
    if (G1) {
        // C col-pair (even, odd) = (gate, up) of output col j
#pragma unroll
        for (int mi = 0; mi < 4; mi++) {
            int r0 = wm + mi * 16 + tr;
            int r1 = r0 + 8;
#pragma unroll
            for (int ni = 0; ni < 8; ni++) {
                int col = nb * 128 + (wn >> 1) + ni * 4 + tc;
                if (r0 < rowsValid) {
                    float g = acc[mi][ni][0], u = acc[mi][ni][1];
                    g_acth[(size_t)(slot0 + r0) * I_DIM + col] =
                        __float2half_rn(g / (1.f + __expf(-g)) * u);
                }
                if (r1 < rowsValid) {
                    float g = acc[mi][ni][2], u = acc[mi][ni][3];
                    g_acth[(size_t)(slot0 + r1) * I_DIM + col] =
                        __float2half_rn(g / (1.f + __expf(-g)) * u);
                }
            }
        }
    } else {
#pragma unroll
        for (int mi = 0; mi < 4; mi++) {
            int r0 = wm + mi * 16 + tr;
            int r1 = r0 + 8;
#pragma unroll
            for (int ni = 0; ni < 8; ni++) {
                int c = nb * 256 + wn + ni * 8 + tc * 2;
                if (r0 < rowsValid) {
                    __half2 v = __floats2half2_rn(acc[mi][ni][0], acc[mi][ni][1]);
                    *(__half2*)&g_yh[(size_t)(slot0 + r0) * H_DIM + c] = v;
                }
                if (r1 < rowsValid) {
                    __half2 v = __floats2half2_rn(acc[mi][ni][2], acc[mi][ni][3]);
                    *(__half2*)&g_yh[(size_t)(slot0 + r1) * H_DIM + c] = v;
                }
            }
        }
    }
}

// ---------------- weighted combine (exactly 2 slots per token) ---------------
__global__ void combine_kernel(float* __restrict__ out) {
    const int per_row = H_DIM / 8;            // 8 halves (16B) per thread-group
    int idx = blockIdx.x * blockDim.x + threadIdx.x;
    if (idx >= T_TOK * per_row) return;
    int t = idx / per_row;
    int h = idx % per_row;
    int p0 = g_slot[2*t], p1 = g_slot[2*t+1];
    float w0 = g_topw[2*t], w1 = g_topw[2*t+1];
    uint4 a = ((const uint4*)&g_yh[(size_t)p0 * H_DIM])[h];
    uint4 b = ((const uint4*)&g_yh[(size_t)p1 * H_DIM])[h];
    float* op = out + (size_t)t * H_DIM + h * 8;
    const uint32_t* ap = &a.x;
    const uint32_t* bp = &b.x;
#pragma unroll
    for (int q = 0; q < 4; q++) {
        float2 fa = __half22float2(*(const __half2*)&ap[q]);
        float2 fb = __half22float2(*(const __half2*)&bp[q]);
        float2 o;
        o.x = w0 * fa.x + w1 * fb.x;
        o.y = w0 * fa.y + w1 * fb.y;
        *(float2*)(op + q * 2) = o;
    }
}

// ---------------- launch -----------------------------------------------------
extern "C" void kernel_launch(void* const* d_in, const int* in_sizes, int n_in,
                              void* d_out, int out_size) {
    (void)in_sizes; (void)n_in; (void)out_size;
    const float* hidden = (const float*)d_in[0];
    const float* logits = (const float*)d_in[1];
    const float* w13    = (const float*)d_in[2];
    const float* w2     = (const float*)d_in[3];
    float* out = (float*)d_out;

    cudaFuncSetAttribute(moe_gemm<H_DIM, true>,
                         cudaFuncAttributeMaxDynamicSharedMemorySize, GEMM_SMEM);
    cudaFuncSetAttribute(moe_gemm<I_DIM, false>,
                         cudaFuncAttributeMaxDynamicSharedMemorySize, GEMM_SMEM);

    init_kernel<<<1, 32>>>();
    route_kernel<<<T_TOK / 256, 256>>>(logits);
    scan_kernel<<<1, 1>>>();
    perm_kernel<<<T_TOK / 256, 256>>>();

    // fp32 -> fp16 operand conversion (device-global staging)
    {
        __half* dxh;  cudaGetSymbolAddress((void**)&dxh,  g_xh);
        __half* dw13; cudaGetSymbolAddress((void**)&dw13, g_w13h);
        __half* dw2;  cudaGetSymbolAddress((void**)&dw2,  g_w2h);
        int n8x  = T_TOK * H_DIM / 8;
        int n8w1 = E_NUM * TWOI * H_DIM / 8;
        int n8w2 = E_NUM * H_DIM * I_DIM / 8;
        cvt_f2h<<<(n8x  + 255) / 256, 256>>>(hidden, dxh,  n8x);
        cvt_f2h<<<(n8w1 + 255) / 256, 256>>>(w13,    dw13, n8w1);
        cvt_f2h<<<(n8w2 + 255) / 256, 256>>>(w2,     dw2,  n8w2);
    }

    // GEMM1 + fused SiLU: g_acth[slot, 1408]
    moe_gemm<H_DIM, true>
        <<<dim3(I_DIM / 128, S_SLOTS / 128, E_NUM), 256, GEMM_SMEM>>>();

    // GEMM2: g_yh[slot, 2048] = act @ w2_e^T (fp16 out)
    moe_gemm<I_DIM, false>
        <<<dim3(H_DIM / 256, S_SLOTS / 128, E_NUM), 256, GEMM_SMEM>>>();

    int nc = T_TOK * (H_DIM / 8);
    combine_kernel<<<(nc + 255) / 256, 256>>>(out);
}

// round 10
// speedup vs baseline: 2.2672x; 1.0268x over previous
#include <cuda_runtime.h>
#include <cuda_fp16.h>
#include <math.h>
#include <stdint.h>

#define T_TOK 16384
#define H_DIM 2048
#define E_NUM 16
#define I_DIM 1408
#define TWOI  2816
#define S_SLOTS (T_TOK*2)

// ---------------- scratch (device globals: no allocations allowed) ----------
__device__ int    g_counts[E_NUM];
__device__ int    g_fill[E_NUM];
__device__ int    g_offs[E_NUM+1];
__device__ int    g_ids[S_SLOTS];
__device__ float  g_topw[S_SLOTS];
__device__ int    g_perm[S_SLOTS];         // slot -> token
__device__ int    g_slot[S_SLOTS];         // (token,k) -> slot
__device__ __half g_xh [(size_t)T_TOK * H_DIM];         // fp16 hidden
__device__ __half g_w13h[(size_t)E_NUM * TWOI * H_DIM]; // fp16 w13
__device__ __half g_w2h [(size_t)E_NUM * H_DIM * I_DIM];// fp16 w2
__device__ __half g_acth[(size_t)S_SLOTS * I_DIM];      // fp16 silu(g)*u
__device__ __half g_yh  [(size_t)S_SLOTS * H_DIM];      // fp16 act @ w2^T

// ---------------- routing ---------------------------------------------------
__global__ void init_kernel() {
    int i = threadIdx.x;
    if (i < E_NUM) { g_counts[i] = 0; g_fill[i] = 0; }
}

__global__ void route_kernel(const float* __restrict__ logits) {
    int t = blockIdx.x * blockDim.x + threadIdx.x;
    if (t >= T_TOK) return;
    float l[E_NUM];
#pragma unroll
    for (int e = 0; e < E_NUM; e++) l[e] = logits[t * E_NUM + e];
    int e0 = 0; float m0 = l[0];
#pragma unroll
    for (int e = 1; e < E_NUM; e++) if (l[e] > m0) { m0 = l[e]; e0 = e; }
    int e1 = -1; float m1 = -1e30f;
#pragma unroll
    for (int e = 0; e < E_NUM; e++) if (e != e0 && l[e] > m1) { m1 = l[e]; e1 = e; }
    float w0 = 1.f / (1.f + expf(m1 - m0));   // renormalized top-2 softmax
    float w1 = 1.f - w0;
    g_ids[2*t] = e0;  g_ids[2*t+1] = e1;
    g_topw[2*t] = w0; g_topw[2*t+1] = w1;
    atomicAdd(&g_counts[e0], 1);
    atomicAdd(&g_counts[e1], 1);
}

__global__ void scan_kernel() {
    if (threadIdx.x == 0) {
        int acc = 0; g_offs[0] = 0;
        for (int e = 0; e < E_NUM; e++) { acc += g_counts[e]; g_offs[e+1] = acc; }
    }
}

__global__ void perm_kernel() {
    int t = blockIdx.x * blockDim.x + threadIdx.x;
    if (t >= T_TOK) return;
#pragma unroll
    for (int s = 0; s < 2; s++) {
        int e = g_ids[2*t+s];
        int pos = g_offs[e] + atomicAdd(&g_fill[e], 1);
        g_perm[pos] = t;
        g_slot[2*t+s] = pos;
    }
}

// ---------------- fp32 -> fp16 bulk convert (8 elems/thread) -----------------
__global__ void cvt_f2h(const float* __restrict__ s, __half* __restrict__ d, int n8) {
    int i = blockIdx.x * blockDim.x + threadIdx.x;
    if (i >= n8) return;
    const float4* sp = (const float4*)s + (size_t)i * 2;
    float4 a = sp[0], b = sp[1];
    __half2 h0 = __floats2half2_rn(a.x, a.y);
    __half2 h1 = __floats2half2_rn(a.z, a.w);
    __half2 h2 = __floats2half2_rn(b.x, b.y);
    __half2 h3 = __floats2half2_rn(b.z, b.w);
    uint4 o;
    o.x = *(uint32_t*)&h0; o.y = *(uint32_t*)&h1;
    o.z = *(uint32_t*)&h2; o.w = *(uint32_t*)&h3;
    ((uint4*)d)[i] = o;
}

// ---------------- mma / ldmatrix helpers -------------------------------------
__device__ __forceinline__ void mma16(float* c, const uint32_t* a, const uint32_t* b) {
    asm volatile(
        "mma.sync.aligned.m16n8k16.row.col.f32.f16.f16.f32 "
        "{%0,%1,%2,%3},{%4,%5,%6,%7},{%8,%9},{%0,%1,%2,%3};"
        : "+f"(c[0]), "+f"(c[1]), "+f"(c[2]), "+f"(c[3])
        : "r"(a[0]), "r"(a[1]), "r"(a[2]), "r"(a[3]), "r"(b[0]), "r"(b[1]));
}
__device__ __forceinline__ void ldm4(uint32_t* r, uint32_t a) {
    asm volatile("ldmatrix.sync.aligned.m8n8.x4.shared.b16 {%0,%1,%2,%3}, [%4];"
                 : "=r"(r[0]), "=r"(r[1]), "=r"(r[2]), "=r"(r[3]) : "r"(a));
}
__device__ __forceinline__ void cpa16(uint32_t dst, const void* src) {
    asm volatile("cp.async.cg.shared.global [%0], [%1], 16;\n" :: "r"(dst), "l"(src));
}
__device__ __forceinline__ uint32_t smem_u32(const void* p) {
    uint32_t a;
    asm("{ .reg .u64 t; cvta.to.shared.u64 t, %1; cvt.u32.u64 %0, t; }"
        : "=r"(a) : "l"(p));
    return a;
}

// ---------------- grouped fp16 GEMM ------------------------------------------
// CTA 128(M) x 256(N), K-stage = 64 halves (two 32-K sub-blocks), 256 threads,
// 8 warps of 64x64. 3-stage cp.async pipeline; fragments via ldmatrix.x4
// (8 LDSM per 32-MMA sub-phase instead of 48 LDS.32), double-buffered so the
// LDSM of sub-phase ks+1 issues before the MMAs of ks. smem rows 80B
// (64B data + 16B pad): ldmatrix's 8 row-addresses hit 8 distinct 16B
// segments mod 128B -> conflict-free.
// G1: A = g_xh[perm[slot]] (K=2048); B rows interleave gate/up of w13 so each
//     thread's C col-pair = (gate, up) of one output col -> fused SiLU into
//     g_acth. G2: A = g_acth (K=1408); B = w2 rows -> g_yh (fp16).
#define A_BYTES 10240               // 128 rows * 80B
#define B_BYTES 20480               // 256 rows * 80B
#define SUB_BYTES (A_BYTES + B_BYTES)        // 30720 (32-K sub-block)
#define STAGE_BYTES (2 * SUB_BYTES)          // 61440 (64-K stage)
#define GEMM_SMEM (3 * STAGE_BYTES)          // 184320

template<int KDIM, bool G1>
__global__ __launch_bounds__(256, 1) void moe_gemm(void)
{
    constexpr int NK = KDIM / 64;             // 64-half (128B) stages
    int e     = blockIdx.z;
    int off   = g_offs[e];
    int cnt   = g_offs[e+1] - off;
    int mbase = blockIdx.y * 128;
    if (mbase >= cnt) return;
    int rowsValid = cnt - mbase;
    int slot0 = off + mbase;
    int nb    = blockIdx.x;

    extern __shared__ char dynsm[];
    uint32_t smbase = smem_u32(dynsm);

    int tid  = threadIdx.x;
    int lane = tid & 31;
    int warp = tid >> 5;

    // A source row (2 threads per row, 32B halves of each 64B sub-row)
    int arr = tid >> 1, ah = tid & 1;
    int slot = slot0 + arr;
    if (slot >= S_SLOTS) slot = S_SLOTS - 1;  // clamp; output masked
    const char* arow;
    if (G1) arow = (const char*)(g_xh + (size_t)g_perm[slot] * KDIM);
    else    arow = (const char*)(g_acth + (size_t)slot * KDIM);
    // B source row (1 thread per row)
    const char* brow;
    if (G1) {
        int jl   = tid >> 1;                  // output col within 128-block
        int type = tid & 1;                   // 0=gate, 1=up
        int grow = nb * 128 + jl + type * I_DIM;
        brow = (const char*)(g_w13h + (size_t)e * TWOI * H_DIM
                                     + (size_t)grow * H_DIM);
    } else {
        brow = (const char*)(g_w2h + (size_t)e * H_DIM * I_DIM
                                    + (size_t)(nb * 256 + tid) * I_DIM);
    }
    uint32_t aoff = (uint32_t)arr * 80 + (uint32_t)ah * 32;
    uint32_t boff = (uint32_t)tid * 80;

    // fill one 64-K stage (two sub-blocks), single commit
#define FILL(kt) {                                                       \
    uint32_t st_ = smbase + ((kt) % 3) * STAGE_BYTES;                    \
    const char* ap_ = arow + (size_t)(kt) * 128 + ah * 32;               \
    const char* bp_ = brow + (size_t)(kt) * 128;                         \
    _Pragma("unroll")                                                    \
    for (int j_ = 0; j_ < 2; j_++) {                                     \
        uint32_t sa_ = st_ + j_ * SUB_BYTES;                             \
        uint32_t sb_ = sa_ + A_BYTES;                                    \
        cpa16(sa_ + aoff,      ap_ + j_ * 64);                           \
        cpa16(sa_ + aoff + 16, ap_ + j_ * 64 + 16);                      \
        cpa16(sb_ + boff,      bp_ + j_ * 64);                           \
        cpa16(sb_ + boff + 16, bp_ + j_ * 64 + 16);                      \
        cpa16(sb_ + boff + 32, bp_ + j_ * 64 + 32);                      \
        cpa16(sb_ + boff + 48, bp_ + j_ * 64 + 48);                      \
    }                                                                    \
    asm volatile("cp.async.commit_group;\n" ::: "memory"); }

    int wm = (warp & 1) * 64;                 // 2(M) x 4(N) warp grid, 64x64
    int wn = (warp >> 1) * 64;
    int tr = lane >> 2;                       // 0..7
    int tc = lane & 3;                        // 0..3

    // ldmatrix lane-address bases (byte offsets within a 32-K sub-block)
    // A, matrix mi: groups g: (g&1)->+8 rows, (g>>1)->+16B k
    // B, pair pr (ni=2pr,2pr+1): (g>>1)->+8 rows, (g&1)->+16B k
    int li = lane & 7, gq = lane >> 3;
    uint32_t a_addr[4], b_addr[4];
#pragma unroll
    for (int mi = 0; mi < 4; mi++) {
        int r = wm + mi * 16 + (gq & 1) * 8 + li;
        a_addr[mi] = (uint32_t)r * 80 + (gq >> 1) * 16;
    }
#pragma unroll
    for (int pr = 0; pr < 4; pr++) {
        int n = wn + pr * 16 + (gq >> 1) * 8 + li;
        b_addr[pr] = A_BYTES + (uint32_t)n * 80 + (gq & 1) * 16;
    }

    float acc[4][8][4];
#pragma unroll
    for (int a = 0; a < 4; a++)
#pragma unroll
        for (int b = 0; b < 8; b++)
#pragma unroll
            for (int c = 0; c < 4; c++) acc[a][b][c] = 0.f;

    uint32_t af[2][4][4], bfr[2][4][4];
    // bfr[p][pr] = {bf[2pr][0], bf[2pr][1], bf[2pr+1][0], bf[2pr+1][1]}
#define LOADF(p, stp, ks) {                                              \
    uint32_t off_ = (stp) + ((ks) >> 1) * SUB_BYTES + ((ks) & 1) * 32;   \
    ldm4(af[p][0], off_ + a_addr[0]);                                    \
    ldm4(af[p][1], off_ + a_addr[1]);                                    \
    ldm4(af[p][2], off_ + a_addr[2]);                                    \
    ldm4(af[p][3], off_ + a_addr[3]);                                    \
    ldm4(bfr[p][0], off_ + b_addr[0]);                                   \
    ldm4(bfr[p][1], off_ + b_addr[1]);                                   \
    ldm4(bfr[p][2], off_ + b_addr[2]);                                   \
    ldm4(bfr[p][3], off_ + b_addr[3]);                                   \
}
#define MMAS(p) {                                                        \
    _Pragma("unroll")                                                    \
    for (int mi_ = 0; mi_ < 4; mi_++)                                    \
        _Pragma("unroll")                                                \
        for (int pr_ = 0; pr_ < 4; pr_++) {                              \
            mma16(acc[mi_][2*pr_    ], af[p][mi_], &bfr[p][pr_][0]);     \
            mma16(acc[mi_][2*pr_ + 1], af[p][mi_], &bfr[p][pr_][2]);     \
        }                                                                \
}

    FILL(0);
    FILL(1);

#pragma unroll 1
    for (int kt = 0; kt < NK; kt++) {
        if (kt + 1 < NK) asm volatile("cp.async.wait_group 1;\n" ::: "memory");
        else             asm volatile("cp.async.wait_group 0;\n" ::: "memory");
        __syncthreads();
        if (kt + 2 < NK) FILL(kt + 2);

        uint32_t stp = smbase + (kt % 3) * STAGE_BYTES;
        LOADF(0, stp, 0);
        LOADF(1, stp, 1);  MMAS(0);
        LOADF(0, stp, 2);  MMAS(1);
        LOADF(1, stp, 3);  MMAS(0);
        MMAS(1);
    }
#undef FILL
#undef LOADF
#undef MMAS

    // ---- epilogue -----------------------------------------------------------
    if (G1) {
        // C col-pair (even, odd) = (gate, up) of output col j
#pragma unroll
        for (int mi = 0; mi < 4; mi++) {
            int r0 = wm + mi * 16 + tr;
            int r1 = r0 + 8;
#pragma unroll
            for (int ni = 0; ni < 8; ni++) {
                int col = nb * 128 + (wn >> 1) + ni * 4 + tc;
                if (r0 < rowsValid) {
                    float g = acc[mi][ni][0], u = acc[mi][ni][1];
                    g_acth[(size_t)(slot0 + r0) * I_DIM + col] =
                        __float2half_rn(g / (1.f + __expf(-g)) * u);
                }
                if (r1 < rowsValid) {
                    float g = acc[mi][ni][2], u = acc[mi][ni][3];
                    g_acth[(size_t)(slot0 + r1) * I_DIM + col] =
                        __float2half_rn(g / (1.f + __expf(-g)) * u);
                }
            }
        }
    } else {
#pragma unroll
        for (int mi = 0; mi < 4; mi++) {
            int r0 = wm + mi * 16 + tr;
            int r1 = r0 + 8;
#pragma unroll
            for (int ni = 0; ni < 8; ni++) {
                int c = nb * 256 + wn + ni * 8 + tc * 2;
                if (r0 < rowsValid) {
                    __half2 v = __floats2half2_rn(acc[mi][ni][0], acc[mi][ni][1]);
                    *(__half2*)&g_yh[(size_t)(slot0 + r0) * H_DIM + c] = v;
                }
                if (r1 < rowsValid) {
                    __half2 v = __floats2half2_rn(acc[mi][ni][2], acc[mi][ni][3]);
                    *(__half2*)&g_yh[(size_t)(slot0 + r1) * H_DIM + c] = v;
                }
            }
        }
    }
}

// ---------------- weighted combine (exactly 2 slots per token) ---------------
__global__ void combine_kernel(float* __restrict__ out) {
    const int per_row = H_DIM / 8;
    int idx = blockIdx.x * blockDim.x + threadIdx.x;
    if (idx >= T_TOK * per_row) return;
    int t = idx / per_row;
    int h = idx % per_row;
    int p0 = g_slot[2*t], p1 = g_slot[2*t+1];
    float w0 = g_topw[2*t], w1 = g_topw[2*t+1];
    uint4 a = ((const uint4*)&g_yh[(size_t)p0 * H_DIM])[h];
    uint4 b = ((const uint4*)&g_yh[(size_t)p1 * H_DIM])[h];
    float* op = out + (size_t)t * H_DIM + h * 8;
    const uint32_t* ap = &a.x;
    const uint32_t* bp = &b.x;
#pragma unroll
    for (int q = 0; q < 4; q++) {
        float2 fa = __half22float2(*(const __half2*)&ap[q]);
        float2 fb = __half22float2(*(const __half2*)&bp[q]);
        float2 o;
        o.x = w0 * fa.x + w1 * fb.x;
        o.y = w0 * fa.y + w1 * fb.y;
        *(float2*)(op + q * 2) = o;
    }
}

// ---------------- launch -----------------------------------------------------
extern "C" void kernel_launch(void* const* d_in, const int* in_sizes, int n_in,
                              void* d_out, int out_size) {
    (void)in_sizes; (void)n_in; (void)out_size;
    const float* hidden = (const float*)d_in[0];
    const float* logits = (const float*)d_in[1];
    const float* w13    = (const float*)d_in[2];
    const float* w2     = (const float*)d_in[3];
    float* out = (float*)d_out;

    cudaFuncSetAttribute(moe_gemm<H_DIM, true>,
                         cudaFuncAttributeMaxDynamicSharedMemorySize, GEMM_SMEM);
    cudaFuncSetAttribute(moe_gemm<I_DIM, false>,
                         cudaFuncAttributeMaxDynamicSharedMemorySize, GEMM_SMEM);

    __half* dxh;  cudaGetSymbolAddress((void**)&dxh,  g_xh);
    __half* dw13; cudaGetSymbolAddress((void**)&dw13, g_w13h);
    __half* dw2;  cudaGetSymbolAddress((void**)&dw2,  g_w2h);
    int n8x  = T_TOK * H_DIM / 8;
    int n8w1 = E_NUM * TWOI * H_DIM / 8;
    int n8w2 = E_NUM * H_DIM * I_DIM / 8;

    // Fork a side stream: cvt of w2 (only needed by GEMM2) overlaps GEMM1.
    // Event fork/join keeps the side stream inside graph capture.
    cudaStream_t sw;
    cudaStreamCreateWithFlags(&sw, cudaStreamNonBlocking);
    cudaEvent_t evF, evJ;
    cudaEventCreateWithFlags(&evF, cudaEventDisableTiming);
    cudaEventCreateWithFlags(&evJ, cudaEventDisableTiming);

    cudaEventRecord(evF, 0);
    cudaStreamWaitEvent(sw, evF, 0);
    cvt_f2h<<<(n8w2 + 255) / 256, 256, 0, sw>>>(w2, dw2, n8w2);
    cudaEventRecord(evJ, sw);

    init_kernel<<<1, 32>>>();
    route_kernel<<<T_TOK / 256, 256>>>(logits);
    scan_kernel<<<1, 1>>>();
    perm_kernel<<<T_TOK / 256, 256>>>();
    cvt_f2h<<<(n8x  + 255) / 256, 256>>>(hidden, dxh,  n8x);
    cvt_f2h<<<(n8w1 + 255) / 256, 256>>>(w13,    dw13, n8w1);

    // GEMM1 + fused SiLU: g_acth[slot, 1408]
    moe_gemm<H_DIM, true>
        <<<dim3(I_DIM / 128, S_SLOTS / 128, E_NUM), 256, GEMM_SMEM>>>();

    // join: w2 conversion must be done before GEMM2
    cudaStreamWaitEvent(0, evJ, 0);

    // GEMM2: g_yh[slot, 2048] = act @ w2_e^T (fp16 out)
    moe_gemm<I_DIM, false>
        <<<dim3(H_DIM / 256, S_SLOTS / 128, E_NUM), 256, GEMM_SMEM>>>();

    int nc = T_TOK * (H_DIM / 8);
    combine_kernel<<<(nc + 255) / 256, 256>>>(out);
}

// round 12
// speedup vs baseline: 2.2710x; 1.0017x over previous
#include <cuda_runtime.h>
#include <cuda_fp16.h>
#include <math.h>
#include <stdint.h>

#define T_TOK 16384
#define H_DIM 2048
#define E_NUM 16
#define I_DIM 1408
#define TWOI  2816
#define S_SLOTS (T_TOK*2)

// ---------------- scratch (device globals: no allocations allowed) ----------
__device__ int    g_counts[E_NUM];
__device__ int    g_fill[E_NUM];
__device__ int    g_offs[E_NUM+1];
__device__ int    g_ids[S_SLOTS];
__device__ float  g_topw[S_SLOTS];
__device__ int    g_perm[S_SLOTS];         // slot -> token
__device__ int    g_slot[S_SLOTS];         // (token,k) -> slot
__device__ __half g_xh [(size_t)T_TOK * H_DIM];         // fp16 hidden
__device__ __half g_w13h[(size_t)E_NUM * TWOI * H_DIM]; // fp16 w13
__device__ __half g_w2h [(size_t)E_NUM * H_DIM * I_DIM];// fp16 w2
__device__ __half g_acth[(size_t)S_SLOTS * I_DIM];      // fp16 silu(g)*u
__device__ __half g_yh  [(size_t)S_SLOTS * H_DIM];      // fp16 act @ w2^T

// ---------------- routing ---------------------------------------------------
__global__ void init_kernel() {
    int i = threadIdx.x;
    if (i < E_NUM) { g_counts[i] = 0; g_fill[i] = 0; }
}

__global__ void route_kernel(const float* __restrict__ logits) {
    int t = blockIdx.x * blockDim.x + threadIdx.x;
    if (t >= T_TOK) return;
    float l[E_NUM];
#pragma unroll
    for (int e = 0; e < E_NUM; e++) l[e] = logits[t * E_NUM + e];
    int e0 = 0; float m0 = l[0];
#pragma unroll
    for (int e = 1; e < E_NUM; e++) if (l[e] > m0) { m0 = l[e]; e0 = e; }
    int e1 = -1; float m1 = -1e30f;
#pragma unroll
    for (int e = 0; e < E_NUM; e++) if (e != e0 && l[e] > m1) { m1 = l[e]; e1 = e; }
    float w0 = 1.f / (1.f + expf(m1 - m0));   // renormalized top-2 softmax
    float w1 = 1.f - w0;
    g_ids[2*t] = e0;  g_ids[2*t+1] = e1;
    g_topw[2*t] = w0; g_topw[2*t+1] = w1;
    atomicAdd(&g_counts[e0], 1);
    atomicAdd(&g_counts[e1], 1);
}

__global__ void scan_kernel() {
    if (threadIdx.x == 0) {
        int acc = 0; g_offs[0] = 0;
        for (int e = 0; e < E_NUM; e++) { acc += g_counts[e]; g_offs[e+1] = acc; }
    }
}

__global__ void perm_kernel() {
    int t = blockIdx.x * blockDim.x + threadIdx.x;
    if (t >= T_TOK) return;
#pragma unroll
    for (int s = 0; s < 2; s++) {
        int e = g_ids[2*t+s];
        int pos = g_offs[e] + atomicAdd(&g_fill[e], 1);
        g_perm[pos] = t;
        g_slot[2*t+s] = pos;
    }
}

// ---------------- fp32 -> fp16 bulk convert (8 elems/thread) -----------------
__global__ void cvt_f2h(const float* __restrict__ s, __half* __restrict__ d, int n8) {
    int i = blockIdx.x * blockDim.x + threadIdx.x;
    if (i >= n8) return;
    const float4* sp = (const float4*)s + (size_t)i * 2;
    float4 a = sp[0], b = sp[1];
    __half2 h0 = __floats2half2_rn(a.x, a.y);
    __half2 h1 = __floats2half2_rn(a.z, a.w);
    __half2 h2 = __floats2half2_rn(b.x, b.y);
    __half2 h3 = __floats2half2_rn(b.z, b.w);
    uint4 o;
    o.x = *(uint32_t*)&h0; o.y = *(uint32_t*)&h1;
    o.z = *(uint32_t*)&h2; o.w = *(uint32_t*)&h3;
    ((uint4*)d)[i] = o;
}

// ---------------- mma / ldmatrix helpers -------------------------------------
__device__ __forceinline__ void mma16(float* c, const uint32_t* a, const uint32_t* b) {
    asm volatile(
        "mma.sync.aligned.m16n8k16.row.col.f32.f16.f16.f32 "
        "{%0,%1,%2,%3},{%4,%5,%6,%7},{%8,%9},{%0,%1,%2,%3};"
        : "+f"(c[0]), "+f"(c[1]), "+f"(c[2]), "+f"(c[3])
        : "r"(a[0]), "r"(a[1]), "r"(a[2]), "r"(a[3]), "r"(b[0]), "r"(b[1]));
}
__device__ __forceinline__ void ldm4(uint32_t* r, uint32_t a) {
    asm volatile("ldmatrix.sync.aligned.m8n8.x4.shared.b16 {%0,%1,%2,%3}, [%4];"
                 : "=r"(r[0]), "=r"(r[1]), "=r"(r[2]), "=r"(r[3]) : "r"(a));
}
__device__ __forceinline__ void cpa16(uint32_t dst, const void* src) {
    asm volatile("cp.async.cg.shared.global [%0], [%1], 16;\n" :: "r"(dst), "l"(src));
}
__device__ __forceinline__ uint32_t smem_u32(const void* p) {
    uint32_t a;
    asm("{ .reg .u64 t; cvta.to.shared.u64 t, %1; cvt.u32.u64 %0, t; }"
        : "=r"(a) : "l"(p));
    return a;
}

// ---------------- grouped fp16 GEMM ------------------------------------------
// CTA 128(M) x 256(N), K-stage = 64 halves (two 32-K sub-blocks), 256 threads,
// 8 warps of 64x64. 3-stage cp.async pipeline; fragments via ldmatrix.x4,
// double-buffered. smem rows 80B (64B data + 16B pad) -> conflict-free LDSM.
// This mainloop measures ~390 MAC/cyc/SM (hardware ceiling of the fallback
// HMMA path on sm_103a) -- left untouched.
// G1: A = g_xh[perm[slot]] (K=2048); B rows interleave gate/up of w13 so each
//     thread's C col-pair = (gate, up) of one output col -> fused SiLU into
//     g_acth. G2: A = g_acth (K=1408); B = w2 rows -> g_yh (fp16).
#define A_BYTES 10240               // 128 rows * 80B
#define B_BYTES 20480               // 256 rows * 80B
#define SUB_BYTES (A_BYTES + B_BYTES)        // 30720 (32-K sub-block)
#define STAGE_BYTES (2 * SUB_BYTES)          // 61440 (64-K stage)
#define GEMM_SMEM (3 * STAGE_BYTES)          // 184320

template<int KDIM, bool G1>
__global__ __launch_bounds__(256, 1) void moe_gemm(void)
{
    constexpr int NK = KDIM / 64;             // 64-half (128B) stages
    int e     = blockIdx.z;
    int off   = g_offs[e];
    int cnt   = g_offs[e+1] - off;
    int mbase = blockIdx.y * 128;
    if (mbase >= cnt) return;
    int rowsValid = cnt - mbase;
    int slot0 = off + mbase;
    int nb    = blockIdx.x;

    extern __shared__ char dynsm[];
    uint32_t smbase = smem_u32(dynsm);

    int tid  = threadIdx.x;
    int lane = tid & 31;
    int warp = tid >> 5;

    // A source row (2 threads per row, 32B halves of each 64B sub-row)
    int arr = tid >> 1, ah = tid & 1;
    int slot = slot0 + arr;
    if (slot >= S_SLOTS) slot = S_SLOTS - 1;  // clamp; output masked
    const char* arow;
    if (G1) arow = (const char*)(g_xh + (size_t)g_perm[slot] * KDIM);
    else    arow = (const char*)(g_acth + (size_t)slot * KDIM);
    // B source row (1 thread per row)
    const char* brow;
    if (G1) {
        int jl   = tid >> 1;                  // output col within 128-block
        int type = tid & 1;                   // 0=gate, 1=up
        int grow = nb * 128 + jl + type * I_DIM;
        brow = (const char*)(g_w13h + (size_t)e * TWOI * H_DIM
                                     + (size_t)grow * H_DIM);
    } else {
        brow = (const char*)(g_w2h + (size_t)e * H_DIM * I_DIM
                                    + (size_t)(nb * 256 + tid) * I_DIM);
    }
    uint32_t aoff = (uint32_t)arr * 80 + (uint32_t)ah * 32;
    uint32_t boff = (uint32_t)tid * 80;

    // fill one 64-K stage (two sub-blocks), single commit
#define FILL(kt) {                                                       \
    uint32_t st_ = smbase + ((kt) % 3) * STAGE_BYTES;                    \
    const char* ap_ = arow + (size_t)(kt) * 128 + ah * 32;               \
    const char* bp_ = brow + (size_t)(kt) * 128;                         \
    _Pragma("unroll")                                                    \
    for (int j_ = 0; j_ < 2; j_++) {                                     \
        uint32_t sa_ = st_ + j_ * SUB_BYTES;                             \
        uint32_t sb_ = sa_ + A_BYTES;                                    \
        cpa16(sa_ + aoff,      ap_ + j_ * 64);                           \
        cpa16(sa_ + aoff + 16, ap_ + j_ * 64 + 16);                      \
        cpa16(sb_ + boff,      bp_ + j_ * 64);                           \
        cpa16(sb_ + boff + 16, bp_ + j_ * 64 + 16);                      \
        cpa16(sb_ + boff + 32, bp_ + j_ * 64 + 32);                      \
        cpa16(sb_ + boff + 48, bp_ + j_ * 64 + 48);                      \
    }                                                                    \
    asm volatile("cp.async.commit_group;\n" ::: "memory"); }

    int wm = (warp & 1) * 64;                 // 2(M) x 4(N) warp grid, 64x64
    int wn = (warp >> 1) * 64;
    int tr = lane >> 2;                       // 0..7
    int tc = lane & 3;                        // 0..3

    // ldmatrix lane-address bases (byte offsets within a 32-K sub-block)
    int li = lane & 7, gq = lane >> 3;
    uint32_t a_addr[4], b_addr[4];
#pragma unroll
    for (int mi = 0; mi < 4; mi++) {
        int r = wm + mi * 16 + (gq & 1) * 8 + li;
        a_addr[mi] = (uint32_t)r * 80 + (gq >> 1) * 16;
    }
#pragma unroll
    for (int pr = 0; pr < 4; pr++) {
        int n = wn + pr * 16 + (gq >> 1) * 8 + li;
        b_addr[pr] = A_BYTES + (uint32_t)n * 80 + (gq & 1) * 16;
    }

    float acc[4][8][4];
#pragma unroll
    for (int a = 0; a < 4; a++)
#pragma unroll
        for (int b = 0; b < 8; b++)
#pragma unroll
            for (int c = 0; c < 4; c++) acc[a][b][c] = 0.f;

    uint32_t af[2][4][4], bfr[2][4][4];
#define LOADF(p, stp, ks) {                                              \
    uint32_t off_ = (stp) + ((ks) >> 1) * SUB_BYTES + ((ks) & 1) * 32;   \
    ldm4(af[p][0], off_ + a_addr[0]);                                    \
    ldm4(af[p][1], off_ + a_addr[1]);                                    \
    ldm4(af[p][2], off_ + a_addr[2]);                                    \
    ldm4(af[p][3], off_ + a_addr[3]);                                    \
    ldm4(bfr[p][0], off_ + b_addr[0]);                                   \
    ldm4(bfr[p][1], off_ + b_addr[1]);                                   \
    ldm4(bfr[p][2], off_ + b_addr[2]);                                   \
    ldm4(bfr[p][3], off_ + b_addr[3]);                                   \
}
#define MMAS(p) {                                                        \
    _Pragma("unroll")                                                    \
    for (int mi_ = 0; mi_ < 4; mi_++)                                    \
        _Pragma("unroll")                                                \
        for (int pr_ = 0; pr_ < 4; pr_++) {                              \
            mma16(acc[mi_][2*pr_    ], af[p][mi_], &bfr[p][pr_][0]);     \
            mma16(acc[mi_][2*pr_ + 1], af[p][mi_], &bfr[p][pr_][2]);     \
        }                                                                \
}

    FILL(0);
    FILL(1);

#pragma unroll 1
    for (int kt = 0; kt < NK; kt++) {
        if (kt + 1 < NK) asm volatile("cp.async.wait_group 1;\n" ::: "memory");
        else             asm volatile("cp.async.wait_group 0;\n" ::: "memory");
        __syncthreads();
        if (kt + 2 < NK) FILL(kt + 2);

        uint32_t stp = smbase + (kt % 3) * STAGE_BYTES;
        LOADF(0, stp, 0);
        LOADF(1, stp, 1);  MMAS(0);
        LOADF(0, stp, 2);  MMAS(1);
        LOADF(1, stp, 3);  MMAS(0);
        MMAS(1);
    }
#undef FILL
#undef LOADF
#undef MMAS

    // ---- epilogue -----------------------------------------------------------
    if (G1) {
        // C col-pair (even, odd) = (gate, up) of output col j
#pragma unroll
        for (int mi = 0; mi < 4; mi++) {
            int r0 = wm + mi * 16 + tr;
            int r1 = r0 + 8;
#pragma unroll
            for (int ni = 0; ni < 8; ni++) {
                int col = nb * 128 + (wn >> 1) + ni * 4 + tc;
                if (r0 < rowsValid) {
                    float g = acc[mi][ni][0], u = acc[mi][ni][1];
                    g_acth[(size_t)(slot0 + r0) * I_DIM + col] =
                        __float2half_rn(g / (1.f + __expf(-g)) * u);
                }
                if (r1 < rowsValid) {
                    float g = acc[mi][ni][2], u = acc[mi][ni][3];
                    g_acth[(size_t)(slot0 + r1) * I_DIM + col] =
                        __float2half_rn(g / (1.f + __expf(-g)) * u);
                }
            }
        }
    } else {
#pragma unroll
        for (int mi = 0; mi < 4; mi++) {
            int r0 = wm + mi * 16 + tr;
            int r1 = r0 + 8;
#pragma unroll
            for (int ni = 0; ni < 8; ni++) {
                int c = nb * 256 + wn + ni * 8 + tc * 2;
                if (r0 < rowsValid) {
                    __half2 v = __floats2half2_rn(acc[mi][ni][0], acc[mi][ni][1]);
                    *(__half2*)&g_yh[(size_t)(slot0 + r0) * H_DIM + c] = v;
                }
                if (r1 < rowsValid) {
                    __half2 v = __floats2half2_rn(acc[mi][ni][2], acc[mi][ni][3]);
                    *(__half2*)&g_yh[(size_t)(slot0 + r1) * H_DIM + c] = v;
                }
            }
        }
    }
}

// ---------------- weighted combine (exactly 2 slots per token) ---------------
__global__ void combine_kernel(float* __restrict__ out) {
    const int per_row = H_DIM / 8;
    int idx = blockIdx.x * blockDim.x + threadIdx.x;
    if (idx >= T_TOK * per_row) return;
    int t = idx / per_row;
    int h = idx % per_row;
    int p0 = g_slot[2*t], p1 = g_slot[2*t+1];
    float w0 = g_topw[2*t], w1 = g_topw[2*t+1];
    uint4 a = ((const uint4*)&g_yh[(size_t)p0 * H_DIM])[h];
    uint4 b = ((const uint4*)&g_yh[(size_t)p1 * H_DIM])[h];
    float* op = out + (size_t)t * H_DIM + h * 8;
    const uint32_t* ap = &a.x;
    const uint32_t* bp = &b.x;
#pragma unroll
    for (int q = 0; q < 4; q++) {
        float2 fa = __half22float2(*(const __half2*)&ap[q]);
        float2 fb = __half22float2(*(const __half2*)&bp[q]);
        float2 o;
        o.x = w0 * fa.x + w1 * fb.x;
        o.y = w0 * fa.y + w1 * fb.y;
        *(float2*)(op + q * 2) = o;
    }
}

// ---------------- launch -----------------------------------------------------
extern "C" void kernel_launch(void* const* d_in, const int* in_sizes, int n_in,
                              void* d_out, int out_size) {
    (void)in_sizes; (void)n_in; (void)out_size;
    const float* hidden = (const float*)d_in[0];
    const float* logits = (const float*)d_in[1];
    const float* w13    = (const float*)d_in[2];
    const float* w2     = (const float*)d_in[3];
    float* out = (float*)d_out;

    cudaFuncSetAttribute(moe_gemm<H_DIM, true>,
                         cudaFuncAttributeMaxDynamicSharedMemorySize, GEMM_SMEM);
    cudaFuncSetAttribute(moe_gemm<I_DIM, false>,
                         cudaFuncAttributeMaxDynamicSharedMemorySize, GEMM_SMEM);

    __half* dxh;  cudaGetSymbolAddress((void**)&dxh,  g_xh);
    __half* dw13; cudaGetSymbolAddress((void**)&dw13, g_w13h);
    __half* dw2;  cudaGetSymbolAddress((void**)&dw2,  g_w2h);
    int n8x  = T_TOK * H_DIM / 8;
    int n8w1 = E_NUM * TWOI * H_DIM / 8;
    int n8w2 = E_NUM * H_DIM * I_DIM / 8;

    // ONE side stream (the configuration proven teardown-clean in R10):
    // it runs both weight conversions back-to-back. w13 cvt overlaps
    // routing + x-conversion on the main stream; w2 cvt overlaps GEMM1.
    cudaStream_t sw;
    cudaStreamCreateWithFlags(&sw, cudaStreamNonBlocking);
    cudaEvent_t evF, evW13, evW2;
    cudaEventCreateWithFlags(&evF,   cudaEventDisableTiming);
    cudaEventCreateWithFlags(&evW13, cudaEventDisableTiming);
    cudaEventCreateWithFlags(&evW2,  cudaEventDisableTiming);

    cudaEventRecord(evF, 0);
    cudaStreamWaitEvent(sw, evF, 0);
    cvt_f2h<<<(n8w1 + 255) / 256, 256, 0, sw>>>(w13, dw13, n8w1);
    cudaEventRecord(evW13, sw);
    cvt_f2h<<<(n8w2 + 255) / 256, 256, 0, sw>>>(w2, dw2, n8w2);
    cudaEventRecord(evW2, sw);

    init_kernel<<<1, 32>>>();
    route_kernel<<<T_TOK / 256, 256>>>(logits);
    scan_kernel<<<1, 1>>>();
    perm_kernel<<<T_TOK / 256, 256>>>();
    cvt_f2h<<<(n8x + 255) / 256, 256>>>(hidden, dxh, n8x);

    // join: w13 conversion must be done before GEMM1
    cudaStreamWaitEvent(0, evW13, 0);

    // GEMM1 + fused SiLU: g_acth[slot, 1408]
    moe_gemm<H_DIM, true>
        <<<dim3(I_DIM / 128, S_SLOTS / 128, E_NUM), 256, GEMM_SMEM>>>();

    // join: w2 conversion must be done before GEMM2
    cudaStreamWaitEvent(0, evW2, 0);

    // GEMM2: g_yh[slot, 2048] = act @ w2_e^T (fp16 out)
    moe_gemm<I_DIM, false>
        <<<dim3(H_DIM / 256, S_SLOTS / 128, E_NUM), 256, GEMM_SMEM>>>();

    int nc = T_TOK * (H_DIM / 8);
    combine_kernel<<<(nc + 255) / 256, 256>>>(out);
}

// round 13
// speedup vs baseline: 2.3078x; 1.0162x over previous
#include <cuda_runtime.h>
#include <cuda_fp16.h>
#include <math.h>
#include <stdint.h>

#define T_TOK 16384
#define H_DIM 2048
#define E_NUM 16
#define I_DIM 1408
#define TWOI  2816
#define S_SLOTS (T_TOK*2)

// ---------------- scratch (device globals: no allocations allowed) ----------
__device__ int    g_counts[E_NUM];
__device__ int    g_fill[E_NUM];
__device__ int    g_offs[E_NUM+1];
__device__ int    g_ids[S_SLOTS];
__device__ float  g_topw[S_SLOTS];
__device__ int    g_perm[S_SLOTS];         // slot -> token
__device__ int    g_slot[S_SLOTS];         // (token,k) -> slot
__device__ __half g_xh [(size_t)T_TOK * H_DIM];         // fp16 hidden
__device__ __half g_w13h[(size_t)E_NUM * TWOI * H_DIM]; // fp16 w13
__device__ __half g_w2h [(size_t)E_NUM * H_DIM * I_DIM];// fp16 w2
__device__ __half g_acth[(size_t)S_SLOTS * I_DIM];      // fp16 silu(g)*u
__device__ __half g_yh  [(size_t)S_SLOTS * H_DIM];      // fp16 act @ w2^T

// ---------------- routing ---------------------------------------------------
__global__ void init_kernel() {
    int i = threadIdx.x;
    if (i < E_NUM) { g_counts[i] = 0; g_fill[i] = 0; }
}

__global__ void route_kernel(const float* __restrict__ logits) {
    int t = blockIdx.x * blockDim.x + threadIdx.x;
    if (t >= T_TOK) return;
    float l[E_NUM];
#pragma unroll
    for (int e = 0; e < E_NUM; e++) l[e] = logits[t * E_NUM + e];
    int e0 = 0; float m0 = l[0];
#pragma unroll
    for (int e = 1; e < E_NUM; e++) if (l[e] > m0) { m0 = l[e]; e0 = e; }
    int e1 = -1; float m1 = -1e30f;
#pragma unroll
    for (int e = 0; e < E_NUM; e++) if (e != e0 && l[e] > m1) { m1 = l[e]; e1 = e; }
    float w0 = 1.f / (1.f + expf(m1 - m0));   // renormalized top-2 softmax
    float w1 = 1.f - w0;
    g_ids[2*t] = e0;  g_ids[2*t+1] = e1;
    g_topw[2*t] = w0; g_topw[2*t+1] = w1;
    atomicAdd(&g_counts[e0], 1);
    atomicAdd(&g_counts[e1], 1);
}

__global__ void scan_kernel() {
    if (threadIdx.x == 0) {
        int acc = 0; g_offs[0] = 0;
        for (int e = 0; e < E_NUM; e++) { acc += g_counts[e]; g_offs[e+1] = acc; }
    }
}

__global__ void perm_kernel() {
    int t = blockIdx.x * blockDim.x + threadIdx.x;
    if (t >= T_TOK) return;
#pragma unroll
    for (int s = 0; s < 2; s++) {
        int e = g_ids[2*t+s];
        int pos = g_offs[e] + atomicAdd(&g_fill[e], 1);
        g_perm[pos] = t;
        g_slot[2*t+s] = pos;
    }
}

// ---------------- fp32 -> fp16 bulk convert (8 elems/thread) -----------------
__global__ void cvt_f2h(const float* __restrict__ s, __half* __restrict__ d, int n8) {
    int i = blockIdx.x * blockDim.x + threadIdx.x;
    if (i >= n8) return;
    const float4* sp = (const float4*)s + (size_t)i * 2;
    float4 a = sp[0], b = sp[1];
    __half2 h0 = __floats2half2_rn(a.x, a.y);
    __half2 h1 = __floats2half2_rn(a.z, a.w);
    __half2 h2 = __floats2half2_rn(b.x, b.y);
    __half2 h3 = __floats2half2_rn(b.z, b.w);
    uint4 o;
    o.x = *(uint32_t*)&h0; o.y = *(uint32_t*)&h1;
    o.z = *(uint32_t*)&h2; o.w = *(uint32_t*)&h3;
    ((uint4*)d)[i] = o;
}

// ---------------- mma / ldmatrix helpers -------------------------------------
__device__ __forceinline__ void mma16(float* c, const uint32_t* a, const uint32_t* b) {
    asm volatile(
        "mma.sync.aligned.m16n8k16.row.col.f32.f16.f16.f32 "
        "{%0,%1,%2,%3},{%4,%5,%6,%7},{%8,%9},{%0,%1,%2,%3};"
        : "+f"(c[0]), "+f"(c[1]), "+f"(c[2]), "+f"(c[3])
        : "r"(a[0]), "r"(a[1]), "r"(a[2]), "r"(a[3]), "r"(b[0]), "r"(b[1]));
}
__device__ __forceinline__ void ldm4(uint32_t* r, uint32_t a) {
    asm volatile("ldmatrix.sync.aligned.m8n8.x4.shared.b16 {%0,%1,%2,%3}, [%4];"
                 : "=r"(r[0]), "=r"(r[1]), "=r"(r[2]), "=r"(r[3]) : "r"(a));
}
__device__ __forceinline__ void cpa16(uint32_t dst, const void* src) {
    asm volatile("cp.async.cg.shared.global [%0], [%1], 16;\n" :: "r"(dst), "l"(src));
}
__device__ __forceinline__ uint32_t smem_u32(const void* p) {
    uint32_t a;
    asm("{ .reg .u64 t; cvta.to.shared.u64 t, %1; cvt.u32.u64 %0, t; }"
        : "=r"(a) : "l"(p));
    return a;
}

// ---------------- grouped fp16 GEMM ------------------------------------------
// CTA 128(M) x 256(N), K-stage = 64 halves (two 32-K sub-blocks), 256 threads,
// 8 warps of 64x64. 3-stage cp.async pipeline; fragments via ldmatrix.x4,
// double-buffered. smem rows 80B (64B data + 16B pad) -> conflict-free LDSM.
// Mainloop measures ~390 MAC/cyc/SM (ceiling of the fallback HMMA path on
// sm_103a) -- untouched. Kernel now covers a 4-expert group: e = ebase + z,
// enabling two-stream expert-group weaving to fill wave-quantization tails.
// G1: A = g_xh[perm[slot]] (K=2048); B rows interleave gate/up of w13 so each
//     thread's C col-pair = (gate, up) of one output col -> fused SiLU into
//     g_acth. G2: A = g_acth (K=1408); B = w2 rows -> g_yh (fp16).
#define A_BYTES 10240               // 128 rows * 80B
#define B_BYTES 20480               // 256 rows * 80B
#define SUB_BYTES (A_BYTES + B_BYTES)        // 30720 (32-K sub-block)
#define STAGE_BYTES (2 * SUB_BYTES)          // 61440 (64-K stage)
#define GEMM_SMEM (3 * STAGE_BYTES)          // 184320

template<int KDIM, bool G1>
__global__ __launch_bounds__(256, 1) void moe_gemm(int ebase)
{
    constexpr int NK = KDIM / 64;             // 64-half (128B) stages
    int e     = ebase + blockIdx.z;
    int off   = g_offs[e];
    int cnt   = g_offs[e+1] - off;
    int mbase = blockIdx.y * 128;
    if (mbase >= cnt) return;
    int rowsValid = cnt - mbase;
    int slot0 = off + mbase;
    int nb    = blockIdx.x;

    extern __shared__ char dynsm[];
    uint32_t smbase = smem_u32(dynsm);

    int tid  = threadIdx.x;
    int lane = tid & 31;
    int warp = tid >> 5;

    // A source row (2 threads per row, 32B halves of each 64B sub-row)
    int arr = tid >> 1, ah = tid & 1;
    int slot = slot0 + arr;
    if (slot >= S_SLOTS) slot = S_SLOTS - 1;  // clamp; output masked
    const char* arow;
    if (G1) arow = (const char*)(g_xh + (size_t)g_perm[slot] * KDIM);
    else    arow = (const char*)(g_acth + (size_t)slot * KDIM);
    // B source row (1 thread per row)
    const char* brow;
    if (G1) {
        int jl   = tid >> 1;                  // output col within 128-block
        int type = tid & 1;                   // 0=gate, 1=up
        int grow = nb * 128 + jl + type * I_DIM;
        brow = (const char*)(g_w13h + (size_t)e * TWOI * H_DIM
                                     + (size_t)grow * H_DIM);
    } else {
        brow = (const char*)(g_w2h + (size_t)e * H_DIM * I_DIM
                                    + (size_t)(nb * 256 + tid) * I_DIM);
    }
    uint32_t aoff = (uint32_t)arr * 80 + (uint32_t)ah * 32;
    uint32_t boff = (uint32_t)tid * 80;

    // fill one 64-K stage (two sub-blocks), single commit
#define FILL(kt) {                                                       \
    uint32_t st_ = smbase + ((kt) % 3) * STAGE_BYTES;                    \
    const char* ap_ = arow + (size_t)(kt) * 128 + ah * 32;               \
    const char* bp_ = brow + (size_t)(kt) * 128;                         \
    _Pragma("unroll")                                                    \
    for (int j_ = 0; j_ < 2; j_++) {                                     \
        uint32_t sa_ = st_ + j_ * SUB_BYTES;                             \
        uint32_t sb_ = sa_ + A_BYTES;                                    \
        cpa16(sa_ + aoff,      ap_ + j_ * 64);                           \
        cpa16(sa_ + aoff + 16, ap_ + j_ * 64 + 16);                      \
        cpa16(sb_ + boff,      bp_ + j_ * 64);                           \
        cpa16(sb_ + boff + 16, bp_ + j_ * 64 + 16);                      \
        cpa16(sb_ + boff + 32, bp_ + j_ * 64 + 32);                      \
        cpa16(sb_ + boff + 48, bp_ + j_ * 64 + 48);                      \
    }                                                                    \
    asm volatile("cp.async.commit_group;\n" ::: "memory"); }

    int wm = (warp & 1) * 64;                 // 2(M) x 4(N) warp grid, 64x64
    int wn = (warp >> 1) * 64;
    int tr = lane >> 2;                       // 0..7
    int tc = lane & 3;                        // 0..3

    // ldmatrix lane-address bases (byte offsets within a 32-K sub-block)
    int li = lane & 7, gq = lane >> 3;
    uint32_t a_addr[4], b_addr[4];
#pragma unroll
    for (int mi = 0; mi < 4; mi++) {
        int r = wm + mi * 16 + (gq & 1) * 8 + li;
        a_addr[mi] = (uint32_t)r * 80 + (gq >> 1) * 16;
    }
#pragma unroll
    for (int pr = 0; pr < 4; pr++) {
        int n = wn + pr * 16 + (gq >> 1) * 8 + li;
        b_addr[pr] = A_BYTES + (uint32_t)n * 80 + (gq & 1) * 16;
    }

    float acc[4][8][4];
#pragma unroll
    for (int a = 0; a < 4; a++)
#pragma unroll
        for (int b = 0; b < 8; b++)
#pragma unroll
            for (int c = 0; c < 4; c++) acc[a][b][c] = 0.f;

    uint32_t af[2][4][4], bfr[2][4][4];
#define LOADF(p, stp, ks) {                                              \
    uint32_t off_ = (stp) + ((ks) >> 1) * SUB_BYTES + ((ks) & 1) * 32;   \
    ldm4(af[p][0], off_ + a_addr[0]);                                    \
    ldm4(af[p][1], off_ + a_addr[1]);                                    \
    ldm4(af[p][2], off_ + a_addr[2]);                                    \
    ldm4(af[p][3], off_ + a_addr[3]);                                    \
    ldm4(bfr[p][0], off_ + b_addr[0]);                                   \
    ldm4(bfr[p][1], off_ + b_addr[1]);                                   \
    ldm4(bfr[p][2], off_ + b_addr[2]);                                   \
    ldm4(bfr[p][3], off_ + b_addr[3]);                                   \
}
#define MMAS(p) {                                                        \
    _Pragma("unroll")                                                    \
    for (int mi_ = 0; mi_ < 4; mi_++)                                    \
        _Pragma("unroll")                                                \
        for (int pr_ = 0; pr_ < 4; pr_++) {                              \
            mma16(acc[mi_][2*pr_    ], af[p][mi_], &bfr[p][pr_][0]);     \
            mma16(acc[mi_][2*pr_ + 1], af[p][mi_], &bfr[p][pr_][2]);     \
        }                                                                \
}

    FILL(0);
    FILL(1);

#pragma unroll 1
    for (int kt = 0; kt < NK; kt++) {
        if (kt + 1 < NK) asm volatile("cp.async.wait_group 1;\n" ::: "memory");
        else             asm volatile("cp.async.wait_group 0;\n" ::: "memory");
        __syncthreads();
        if (kt + 2 < NK) FILL(kt + 2);

        uint32_t stp = smbase + (kt % 3) * STAGE_BYTES;
        LOADF(0, stp, 0);
        LOADF(1, stp, 1);  MMAS(0);
        LOADF(0, stp, 2);  MMAS(1);
        LOADF(1, stp, 3);  MMAS(0);
        MMAS(1);
    }
#undef FILL
#undef LOADF
#undef MMAS

    // ---- epilogue -----------------------------------------------------------
    if (G1) {
        // C col-pair (even, odd) = (gate, up) of output col j
#pragma unroll
        for (int mi = 0; mi < 4; mi++) {
            int r0 = wm + mi * 16 + tr;
            int r1 = r0 + 8;
#pragma unroll
            for (int ni = 0; ni < 8; ni++) {
                int col = nb * 128 + (wn >> 1) + ni * 4 + tc;
                if (r0 < rowsValid) {
                    float g = acc[mi][ni][0], u = acc[mi][ni][1];
                    g_acth[(size_t)(slot0 + r0) * I_DIM + col] =
                        __float2half_rn(g / (1.f + __expf(-g)) * u);
                }
                if (r1 < rowsValid) {
                    float g = acc[mi][ni][2], u = acc[mi][ni][3];
                    g_acth[(size_t)(slot0 + r1) * I_DIM + col] =
                        __float2half_rn(g / (1.f + __expf(-g)) * u);
                }
            }
        }
    } else {
#pragma unroll
        for (int mi = 0; mi < 4; mi++) {
            int r0 = wm + mi * 16 + tr;
            int r1 = r0 + 8;
#pragma unroll
            for (int ni = 0; ni < 8; ni++) {
                int c = nb * 256 + wn + ni * 8 + tc * 2;
                if (r0 < rowsValid) {
                    __half2 v = __floats2half2_rn(acc[mi][ni][0], acc[mi][ni][1]);
                    *(__half2*)&g_yh[(size_t)(slot0 + r0) * H_DIM + c] = v;
                }
                if (r1 < rowsValid) {
                    __half2 v = __floats2half2_rn(acc[mi][ni][2], acc[mi][ni][3]);
                    *(__half2*)&g_yh[(size_t)(slot0 + r1) * H_DIM + c] = v;
                }
            }
        }
    }
}

// ---------------- weighted combine (exactly 2 slots per token) ---------------
__global__ void combine_kernel(float* __restrict__ out) {
    const int per_row = H_DIM / 8;
    int idx = blockIdx.x * blockDim.x + threadIdx.x;
    if (idx >= T_TOK * per_row) return;
    int t = idx / per_row;
    int h = idx % per_row;
    int p0 = g_slot[2*t], p1 = g_slot[2*t+1];
    float w0 = g_topw[2*t], w1 = g_topw[2*t+1];
    uint4 a = ((const uint4*)&g_yh[(size_t)p0 * H_DIM])[h];
    uint4 b = ((const uint4*)&g_yh[(size_t)p1 * H_DIM])[h];
    float* op = out + (size_t)t * H_DIM + h * 8;
    const uint32_t* ap = &a.x;
    const uint32_t* bp = &b.x;
#pragma unroll
    for (int q = 0; q < 4; q++) {
        float2 fa = __half22float2(*(const __half2*)&ap[q]);
        float2 fb = __half22float2(*(const __half2*)&bp[q]);
        float2 o;
        o.x = w0 * fa.x + w1 * fb.x;
        o.y = w0 * fa.y + w1 * fb.y;
        *(float2*)(op + q * 2) = o;
    }
}

// ---------------- launch -----------------------------------------------------
extern "C" void kernel_launch(void* const* d_in, const int* in_sizes, int n_in,
                              void* d_out, int out_size) {
    (void)in_sizes; (void)n_in; (void)out_size;
    const float* hidden = (const float*)d_in[0];
    const float* logits = (const float*)d_in[1];
    const float* w13    = (const float*)d_in[2];
    const float* w2     = (const float*)d_in[3];
    float* out = (float*)d_out;

    cudaFuncSetAttribute(moe_gemm<H_DIM, true>,
                         cudaFuncAttributeMaxDynamicSharedMemorySize, GEMM_SMEM);
    cudaFuncSetAttribute(moe_gemm<I_DIM, false>,
                         cudaFuncAttributeMaxDynamicSharedMemorySize, GEMM_SMEM);

    __half* dxh;  cudaGetSymbolAddress((void**)&dxh,  g_xh);
    __half* dw13; cudaGetSymbolAddress((void**)&dw13, g_w13h);
    __half* dw2;  cudaGetSymbolAddress((void**)&dw2,  g_w2h);
    int n8x  = T_TOK * H_DIM / 8;
    int n8w1 = E_NUM * TWOI * H_DIM / 8;
    int n8w2 = E_NUM * H_DIM * I_DIM / 8;

    // One side stream (proven teardown-clean envelope). Expert-group weave:
    //   M: routing+cvt_x, G1(g0), G1(g2), G2(g1), G2(g3), combine
    //   S: cvt_w13, cvt_w2, G1(g1), G1(g3), G2(g0), G2(g2)
    // G2(g) waits only on the matching G1(g) event from the other stream, so
    // ready G2 CTAs backfill the other stream's G1 wave-quantization tail.
    cudaStream_t sw;
    cudaStreamCreateWithFlags(&sw, cudaStreamNonBlocking);
    cudaEvent_t evF, evW13, evPre, eg[4], evS;
    cudaEventCreateWithFlags(&evF,   cudaEventDisableTiming);
    cudaEventCreateWithFlags(&evW13, cudaEventDisableTiming);
    cudaEventCreateWithFlags(&evPre, cudaEventDisableTiming);
    for (int i = 0; i < 4; i++) cudaEventCreateWithFlags(&eg[i], cudaEventDisableTiming);
    cudaEventCreateWithFlags(&evS,   cudaEventDisableTiming);

    dim3 grid1(I_DIM / 128, S_SLOTS / 128, 4);   // 4 experts per launch
    dim3 grid2(H_DIM / 256, S_SLOTS / 128, 4);

    // ---- side stream: weight conversions, then its share of GEMM groups ----
    cudaEventRecord(evF, 0);
    cudaStreamWaitEvent(sw, evF, 0);
    cvt_f2h<<<(n8w1 + 255) / 256, 256, 0, sw>>>(w13, dw13, n8w1);
    cudaEventRecord(evW13, sw);
    cvt_f2h<<<(n8w2 + 255) / 256, 256, 0, sw>>>(w2, dw2, n8w2);

    // ---- main stream: routing + x conversion --------------------------------
    init_kernel<<<1, 32>>>();
    route_kernel<<<T_TOK / 256, 256>>>(logits);
    scan_kernel<<<1, 1>>>();
    perm_kernel<<<T_TOK / 256, 256>>>();
    cvt_f2h<<<(n8x + 255) / 256, 256>>>(hidden, dxh, n8x);
    cudaEventRecord(evPre, 0);                 // routing + g_xh ready

    // ---- GEMM weave ---------------------------------------------------------
    // S needs routing/g_xh for its G1 groups; M needs w13 for its G1 groups.
    cudaStreamWaitEvent(sw, evPre, 0);
    cudaStreamWaitEvent(0, evW13, 0);

    moe_gemm<H_DIM, true><<<grid1, 256, GEMM_SMEM, 0>>>(0);    // G1 g0
    cudaEventRecord(eg[0], 0);
    moe_gemm<H_DIM, true><<<grid1, 256, GEMM_SMEM, sw>>>(4);   // G1 g1
    cudaEventRecord(eg[1], sw);
    moe_gemm<H_DIM, true><<<grid1, 256, GEMM_SMEM, 0>>>(8);    // G1 g2
    cudaEventRecord(eg[2], 0);
    moe_gemm<H_DIM, true><<<grid1, 256, GEMM_SMEM, sw>>>(12);  // G1 g3
    cudaEventRecord(eg[3], sw);

    cudaStreamWaitEvent(sw, eg[0], 0);
    moe_gemm<I_DIM, false><<<grid2, 256, GEMM_SMEM, sw>>>(0);  // G2 g0
    cudaStreamWaitEvent(0, eg[1], 0);
    moe_gemm<I_DIM, false><<<grid2, 256, GEMM_SMEM, 0>>>(4);   // G2 g1
    cudaStreamWaitEvent(sw, eg[2], 0);
    moe_gemm<I_DIM, false><<<grid2, 256, GEMM_SMEM, sw>>>(8);  // G2 g2
    cudaEventRecord(evS, sw);
    cudaStreamWaitEvent(0, eg[3], 0);
    moe_gemm<I_DIM, false><<<grid2, 256, GEMM_SMEM, 0>>>(12);  // G2 g3

    // ---- combine: needs all G2 groups --------------------------------------
    cudaStreamWaitEvent(0, evS, 0);
    int nc = T_TOK * (H_DIM / 8);
    combine_kernel<<<(nc + 255) / 256, 256>>>(out);
}

// round 15
// speedup vs baseline: 2.3081x; 1.0001x over previous
#include <cuda_runtime.h>
#include <cuda_fp16.h>
#include <math.h>
#include <stdint.h>

#define T_TOK 16384
#define H_DIM 2048
#define E_NUM 16
#define I_DIM 1408
#define TWOI  2816
#define S_SLOTS (T_TOK*2)

// ---------------- scratch (device globals: no allocations allowed) ----------
__device__ int    g_counts[E_NUM];
__device__ int    g_fill[E_NUM];
__device__ int    g_offs[E_NUM+1];
__device__ int    g_ids[S_SLOTS];
__device__ float  g_topw[S_SLOTS];
__device__ int    g_perm[S_SLOTS];         // slot -> token
__device__ int    g_slot[S_SLOTS];         // (token,k) -> slot
__device__ __half g_xh [(size_t)T_TOK * H_DIM];         // fp16 hidden
__device__ __half g_w13h[(size_t)E_NUM * TWOI * H_DIM]; // fp16 w13
__device__ __half g_w2h [(size_t)E_NUM * H_DIM * I_DIM];// fp16 w2
__device__ __half g_acth[(size_t)S_SLOTS * I_DIM];      // fp16 silu(g)*u
__device__ __half g_yh  [(size_t)S_SLOTS * H_DIM];      // fp16 act @ w2^T

// ---------------- routing ---------------------------------------------------
__global__ void init_kernel() {
    int i = threadIdx.x;
    if (i < E_NUM) { g_counts[i] = 0; g_fill[i] = 0; }
}

__global__ void route_kernel(const float* __restrict__ logits) {
    int t = blockIdx.x * blockDim.x + threadIdx.x;
    if (t >= T_TOK) return;
    float l[E_NUM];
#pragma unroll
    for (int e = 0; e < E_NUM; e++) l[e] = logits[t * E_NUM + e];
    int e0 = 0; float m0 = l[0];
#pragma unroll
    for (int e = 1; e < E_NUM; e++) if (l[e] > m0) { m0 = l[e]; e0 = e; }
    int e1 = -1; float m1 = -1e30f;
#pragma unroll
    for (int e = 0; e < E_NUM; e++) if (e != e0 && l[e] > m1) { m1 = l[e]; e1 = e; }
    float w0 = 1.f / (1.f + expf(m1 - m0));   // renormalized top-2 softmax
    float w1 = 1.f - w0;
    g_ids[2*t] = e0;  g_ids[2*t+1] = e1;
    g_topw[2*t] = w0; g_topw[2*t+1] = w1;
    atomicAdd(&g_counts[e0], 1);
    atomicAdd(&g_counts[e1], 1);
}

__global__ void scan_kernel() {
    if (threadIdx.x == 0) {
        int acc = 0; g_offs[0] = 0;
        for (int e = 0; e < E_NUM; e++) { acc += g_counts[e]; g_offs[e+1] = acc; }
    }
}

__global__ void perm_kernel() {
    int t = blockIdx.x * blockDim.x + threadIdx.x;
    if (t >= T_TOK) return;
#pragma unroll
    for (int s = 0; s < 2; s++) {
        int e = g_ids[2*t+s];
        int pos = g_offs[e] + atomicAdd(&g_fill[e], 1);
        g_perm[pos] = t;
        g_slot[2*t+s] = pos;
    }
}

// ---------------- fp32 -> fp16 bulk convert (8 elems/thread) -----------------
__global__ void cvt_f2h(const float* __restrict__ s, __half* __restrict__ d, int n8) {
    int i = blockIdx.x * blockDim.x + threadIdx.x;
    if (i >= n8) return;
    const float4* sp = (const float4*)s + (size_t)i * 2;
    float4 a = sp[0], b = sp[1];
    __half2 h0 = __floats2half2_rn(a.x, a.y);
    __half2 h1 = __floats2half2_rn(a.z, a.w);
    __half2 h2 = __floats2half2_rn(b.x, b.y);
    __half2 h3 = __floats2half2_rn(b.z, b.w);
    uint4 o;
    o.x = *(uint32_t*)&h0; o.y = *(uint32_t*)&h1;
    o.z = *(uint32_t*)&h2; o.w = *(uint32_t*)&h3;
    ((uint4*)d)[i] = o;
}

// ---------------- mma / ldmatrix helpers -------------------------------------
__device__ __forceinline__ void mma16(float* c, const uint32_t* a, const uint32_t* b) {
    asm volatile(
        "mma.sync.aligned.m16n8k16.row.col.f32.f16.f16.f32 "
        "{%0,%1,%2,%3},{%4,%5,%6,%7},{%8,%9},{%0,%1,%2,%3};"
        : "+f"(c[0]), "+f"(c[1]), "+f"(c[2]), "+f"(c[3])
        : "r"(a[0]), "r"(a[1]), "r"(a[2]), "r"(a[3]), "r"(b[0]), "r"(b[1]));
}
__device__ __forceinline__ void ldm4(uint32_t* r, uint32_t a) {
    asm volatile("ldmatrix.sync.aligned.m8n8.x4.shared.b16 {%0,%1,%2,%3}, [%4];"
                 : "=r"(r[0]), "=r"(r[1]), "=r"(r[2]), "=r"(r[3]) : "r"(a));
}
__device__ __forceinline__ void cpa16(uint32_t dst, const void* src) {
    asm volatile("cp.async.cg.shared.global [%0], [%1], 16;\n" :: "r"(dst), "l"(src));
}
__device__ __forceinline__ uint32_t smem_u32(const void* p) {
    uint32_t a;
    asm("{ .reg .u64 t; cvta.to.shared.u64 t, %1; cvt.u32.u64 %0, t; }"
        : "=r"(a) : "l"(p));
    return a;
}

// ---------------- grouped fp16 GEMM ------------------------------------------
// CTA 128(M) x 256(N), K-stage = 64 halves (two 32-K sub-blocks), 256 threads,
// 8 warps of 64x64. 3-stage cp.async pipeline; fragments via ldmatrix.x4,
// double-buffered. smem rows 80B (64B data + 16B pad) -> conflict-free LDSM.
// Mainloop measures ~390 MAC/cyc/SM (ceiling of the fallback HMMA path on
// sm_103a) -- untouched. Kernel covers a 4-expert group: e = ebase + z,
// enabling two-stream expert-group weaving to fill wave-quantization tails.
// G1: A = g_xh[perm[slot]] (K=2048); B rows interleave gate/up of w13 so each
//     thread's C col-pair = (gate, up) of one output col -> fused SiLU into
//     g_acth. G2: A = g_acth (K=1408); B = w2 rows -> g_yh (fp16).
#define A_BYTES 10240               // 128 rows * 80B
#define B_BYTES 20480               // 256 rows * 80B
#define SUB_BYTES (A_BYTES + B_BYTES)        // 30720 (32-K sub-block)
#define STAGE_BYTES (2 * SUB_BYTES)          // 61440 (64-K stage)
#define GEMM_SMEM (3 * STAGE_BYTES)          // 184320

template<int KDIM, bool G1>
__global__ __launch_bounds__(256, 1) void moe_gemm(int ebase)
{
    constexpr int NK = KDIM / 64;             // 64-half (128B) stages
    int e     = ebase + blockIdx.z;
    int off   = g_offs[e];
    int cnt   = g_offs[e+1] - off;
    int mbase = blockIdx.y * 128;
    if (mbase >= cnt) return;
    int rowsValid = cnt - mbase;
    int slot0 = off + mbase;
    int nb    = blockIdx.x;

    extern __shared__ char dynsm[];
    uint32_t smbase = smem_u32(dynsm);

    int tid  = threadIdx.x;
    int lane = tid & 31;
    int warp = tid >> 5;

    // A source row (2 threads per row, 32B halves of each 64B sub-row)
    int arr = tid >> 1, ah = tid & 1;
    int slot = slot0 + arr;
    if (slot >= S_SLOTS) slot = S_SLOTS - 1;  // clamp; output masked
    const char* arow;
    if (G1) arow = (const char*)(g_xh + (size_t)g_perm[slot] * KDIM);
    else    arow = (const char*)(g_acth + (size_t)slot * KDIM);
    // B source row (1 thread per row)
    const char* brow;
    if (G1) {
        int jl   = tid >> 1;                  // output col within 128-block
        int type = tid & 1;                   // 0=gate, 1=up
        int grow = nb * 128 + jl + type * I_DIM;
        brow = (const char*)(g_w13h + (size_t)e * TWOI * H_DIM
                                     + (size_t)grow * H_DIM);
    } else {
        brow = (const char*)(g_w2h + (size_t)e * H_DIM * I_DIM
                                    + (size_t)(nb * 256 + tid) * I_DIM);
    }
    uint32_t aoff = (uint32_t)arr * 80 + (uint32_t)ah * 32;
    uint32_t boff = (uint32_t)tid * 80;

    // fill one 64-K stage (two sub-blocks), single commit
#define FILL(kt) {                                                       \
    uint32_t st_ = smbase + ((kt) % 3) * STAGE_BYTES;                    \
    const char* ap_ = arow + (size_t)(kt) * 128 + ah * 32;               \
    const char* bp_ = brow + (size_t)(kt) * 128;                         \
    _Pragma("unroll")                                                    \
    for (int j_ = 0; j_ < 2; j_++) {                                     \
        uint32_t sa_ = st_ + j_ * SUB_BYTES;                             \
        uint32_t sb_ = sa_ + A_BYTES;                                    \
        cpa16(sa_ + aoff,      ap_ + j_ * 64);                           \
        cpa16(sa_ + aoff + 16, ap_ + j_ * 64 + 16);                      \
        cpa16(sb_ + boff,      bp_ + j_ * 64);                           \
        cpa16(sb_ + boff + 16, bp_ + j_ * 64 + 16);                      \
        cpa16(sb_ + boff + 32, bp_ + j_ * 64 + 32);                      \
        cpa16(sb_ + boff + 48, bp_ + j_ * 64 + 48);                      \
    }                                                                    \
    asm volatile("cp.async.commit_group;\n" ::: "memory"); }

    int wm = (warp & 1) * 64;                 // 2(M) x 4(N) warp grid, 64x64
    int wn = (warp >> 1) * 64;
    int tr = lane >> 2;                       // 0..7
    int tc = lane & 3;                        // 0..3

    // ldmatrix lane-address bases (byte offsets within a 32-K sub-block)
    int li = lane & 7, gq = lane >> 3;
    uint32_t a_addr[4], b_addr[4];
#pragma unroll
    for (int mi = 0; mi < 4; mi++) {
        int r = wm + mi * 16 + (gq & 1) * 8 + li;
        a_addr[mi] = (uint32_t)r * 80 + (gq >> 1) * 16;
    }
#pragma unroll
    for (int pr = 0; pr < 4; pr++) {
        int n = wn + pr * 16 + (gq >> 1) * 8 + li;
        b_addr[pr] = A_BYTES + (uint32_t)n * 80 + (gq & 1) * 16;
    }

    float acc[4][8][4];
#pragma unroll
    for (int a = 0; a < 4; a++)
#pragma unroll
        for (int b = 0; b < 8; b++)
#pragma unroll
            for (int c = 0; c < 4; c++) acc[a][b][c] = 0.f;

    uint32_t af[2][4][4], bfr[2][4][4];
#define LOADF(p, stp, ks) {                                              \
    uint32_t off_ = (stp) + ((ks) >> 1) * SUB_BYTES + ((ks) & 1) * 32;   \
    ldm4(af[p][0], off_ + a_addr[0]);                                    \
    ldm4(af[p][1], off_ + a_addr[1]);                                    \
    ldm4(af[p][2], off_ + a_addr[2]);                                    \
    ldm4(af[p][3], off_ + a_addr[3]);                                    \
    ldm4(bfr[p][0], off_ + b_addr[0]);                                   \
    ldm4(bfr[p][1], off_ + b_addr[1]);                                   \
    ldm4(bfr[p][2], off_ + b_addr[2]);                                   \
    ldm4(bfr[p][3], off_ + b_addr[3]);                                   \
}
#define MMAS(p) {                                                        \
    _Pragma("unroll")                                                    \
    for (int mi_ = 0; mi_ < 4; mi_++)                                    \
        _Pragma("unroll")                                                \
        for (int pr_ = 0; pr_ < 4; pr_++) {                              \
            mma16(acc[mi_][2*pr_    ], af[p][mi_], &bfr[p][pr_][0]);     \
            mma16(acc[mi_][2*pr_ + 1], af[p][mi_], &bfr[p][pr_][2]);     \
        }                                                                \
}

    FILL(0);
    FILL(1);

#pragma unroll 1
    for (int kt = 0; kt < NK; kt++) {
        if (kt + 1 < NK) asm volatile("cp.async.wait_group 1;\n" ::: "memory");
        else             asm volatile("cp.async.wait_group 0;\n" ::: "memory");
        __syncthreads();
        if (kt + 2 < NK) FILL(kt + 2);

        uint32_t stp = smbase + (kt % 3) * STAGE_BYTES;
        LOADF(0, stp, 0);
        LOADF(1, stp, 1);  MMAS(0);
        LOADF(0, stp, 2);  MMAS(1);
        LOADF(1, stp, 3);  MMAS(0);
        MMAS(1);
    }
#undef FILL
#undef LOADF
#undef MMAS

    // ---- epilogue -----------------------------------------------------------
    if (G1) {
        // C col-pair (even, odd) = (gate, up) of output col j
#pragma unroll
        for (int mi = 0; mi < 4; mi++) {
            int r0 = wm + mi * 16 + tr;
            int r1 = r0 + 8;
#pragma unroll
            for (int ni = 0; ni < 8; ni++) {
                int col = nb * 128 + (wn >> 1) + ni * 4 + tc;
                if (r0 < rowsValid) {
                    float g = acc[mi][ni][0], u = acc[mi][ni][1];
                    g_acth[(size_t)(slot0 + r0) * I_DIM + col] =
                        __float2half_rn(g / (1.f + __expf(-g)) * u);
                }
                if (r1 < rowsValid) {
                    float g = acc[mi][ni][2], u = acc[mi][ni][3];
                    g_acth[(size_t)(slot0 + r1) * I_DIM + col] =
                        __float2half_rn(g / (1.f + __expf(-g)) * u);
                }
            }
        }
    } else {
#pragma unroll
        for (int mi = 0; mi < 4; mi++) {
            int r0 = wm + mi * 16 + tr;
            int r1 = r0 + 8;
#pragma unroll
            for (int ni = 0; ni < 8; ni++) {
                int c = nb * 256 + wn + ni * 8 + tc * 2;
                if (r0 < rowsValid) {
                    __half2 v = __floats2half2_rn(acc[mi][ni][0], acc[mi][ni][1]);
                    *(__half2*)&g_yh[(size_t)(slot0 + r0) * H_DIM + c] = v;
                }
                if (r1 < rowsValid) {
                    __half2 v = __floats2half2_rn(acc[mi][ni][2], acc[mi][ni][3]);
                    *(__half2*)&g_yh[(size_t)(slot0 + r1) * H_DIM + c] = v;
                }
            }
        }
    }
}

// ---------------- weighted combine (exactly 2 slots per token) ---------------
__global__ void combine_kernel(float* __restrict__ out) {
    const int per_row = H_DIM / 8;
    int idx = blockIdx.x * blockDim.x + threadIdx.x;
    if (idx >= T_TOK * per_row) return;
    int t = idx / per_row;
    int h = idx % per_row;
    int p0 = g_slot[2*t], p1 = g_slot[2*t+1];
    float w0 = g_topw[2*t], w1 = g_topw[2*t+1];
    uint4 a = ((const uint4*)&g_yh[(size_t)p0 * H_DIM])[h];
    uint4 b = ((const uint4*)&g_yh[(size_t)p1 * H_DIM])[h];
    float* op = out + (size_t)t * H_DIM + h * 8;
    const uint32_t* ap = &a.x;
    const uint32_t* bp = &b.x;
#pragma unroll
    for (int q = 0; q < 4; q++) {
        float2 fa = __half22float2(*(const __half2*)&ap[q]);
        float2 fb = __half22float2(*(const __half2*)&bp[q]);
        float2 o;
        o.x = w0 * fa.x + w1 * fb.x;
        o.y = w0 * fa.y + w1 * fb.y;
        *(float2*)(op + q * 2) = o;
    }
}

// ---------------- launch -----------------------------------------------------
extern "C" void kernel_launch(void* const* d_in, const int* in_sizes, int n_in,
                              void* d_out, int out_size) {
    (void)in_sizes; (void)n_in; (void)out_size;
    const float* hidden = (const float*)d_in[0];
    const float* logits = (const float*)d_in[1];
    const float* w13    = (const float*)d_in[2];
    const float* w2     = (const float*)d_in[3];
    float* out = (float*)d_out;

    cudaFuncSetAttribute(moe_gemm<H_DIM, true>,
                         cudaFuncAttributeMaxDynamicSharedMemorySize, GEMM_SMEM);
    cudaFuncSetAttribute(moe_gemm<I_DIM, false>,
                         cudaFuncAttributeMaxDynamicSharedMemorySize, GEMM_SMEM);

    __half* dxh;  cudaGetSymbolAddress((void**)&dxh,  g_xh);
    __half* dw13; cudaGetSymbolAddress((void**)&dw13, g_w13h);
    __half* dw2;  cudaGetSymbolAddress((void**)&dw2,  g_w2h);
    int n8x  = T_TOK * H_DIM / 8;
    int n8w2 = E_NUM * H_DIM * I_DIM / 8;
    // per-group w13 chunk: 4 experts
    const size_t w13g = (size_t)4 * TWOI * H_DIM;      // floats per group
    int n8c = (int)(w13g / 8);

    // One side stream (proven teardown-clean envelope).
    //   S: cvt_x, w13 chunks g0..g3 (events after g0 and g2), cvt_w2,
    //      G1(g1), G1(g3), G2(g0), G2(g2)
    //   M: routing -> evPre; G1(g0) [waits evC0], G1(g2) [waits evC2],
    //      G2(g1), G2(g3), combine
    // G1(g) on main depends only on its own w13 chunk -> first GEMM starts
    // ~30 us earlier than with the monolithic w13 conversion.
    cudaStream_t sw;
    cudaStreamCreateWithFlags(&sw, cudaStreamNonBlocking);
    cudaEvent_t evF, evC0, evC2, evPre, eg[4], evS;
    cudaEventCreateWithFlags(&evF,   cudaEventDisableTiming);
    cudaEventCreateWithFlags(&evC0,  cudaEventDisableTiming);
    cudaEventCreateWithFlags(&evC2,  cudaEventDisableTiming);
    cudaEventCreateWithFlags(&evPre, cudaEventDisableTiming);
    for (int i = 0; i < 4; i++) cudaEventCreateWithFlags(&eg[i], cudaEventDisableTiming);
    cudaEventCreateWithFlags(&evS,   cudaEventDisableTiming);

    dim3 grid1(I_DIM / 128, S_SLOTS / 128, 4);   // 4 experts per launch
    dim3 grid2(H_DIM / 256, S_SLOTS / 128, 4);

    // ---- side stream: x + chunked w13 + w2 conversions ----------------------
    cudaEventRecord(evF, 0);
    cudaStreamWaitEvent(sw, evF, 0);
    cvt_f2h<<<(n8x + 255) / 256, 256, 0, sw>>>(hidden, dxh, n8x);
    cvt_f2h<<<(n8c + 255) / 256, 256, 0, sw>>>(w13 + 0 * w13g, dw13 + 0 * w13g, n8c);
    cudaEventRecord(evC0, sw);                 // x + w13 experts 0-3 ready
    cvt_f2h<<<(n8c + 255) / 256, 256, 0, sw>>>(w13 + 1 * w13g, dw13 + 1 * w13g, n8c);
    cvt_f2h<<<(n8c + 255) / 256, 256, 0, sw>>>(w13 + 2 * w13g, dw13 + 2 * w13g, n8c);
    cudaEventRecord(evC2, sw);                 // ... experts 8-11 ready
    cvt_f2h<<<(n8c + 255) / 256, 256, 0, sw>>>(w13 + 3 * w13g, dw13 + 3 * w13g, n8c);
    cvt_f2h<<<(n8w2 + 255) / 256, 256, 0, sw>>>(w2, dw2, n8w2);  // hides under GEMM1

    // ---- main stream: routing ----------------------------------------------
    init_kernel<<<1, 32>>>();
    route_kernel<<<T_TOK / 256, 256>>>(logits);
    scan_kernel<<<1, 1>>>();
    perm_kernel<<<T_TOK / 256, 256>>>();
    cudaEventRecord(evPre, 0);                 // routing tables ready

    // ---- GEMM weave ---------------------------------------------------------
    cudaStreamWaitEvent(sw, evPre, 0);         // side G1s need routing
    cudaStreamWaitEvent(0, evC0, 0);           // main G1(g0) needs x + w13 g0

    moe_gemm<H_DIM, true><<<grid1, 256, GEMM_SMEM, 0>>>(0);    // G1 g0
    cudaEventRecord(eg[0], 0);
    moe_gemm<H_DIM, true><<<grid1, 256, GEMM_SMEM, sw>>>(4);   // G1 g1
    cudaEventRecord(eg[1], sw);
    cudaStreamWaitEvent(0, evC2, 0);           // main G1(g2) needs w13 g2
    moe_gemm<H_DIM, true><<<grid1, 256, GEMM_SMEM, 0>>>(8);    // G1 g2
    cudaEventRecord(eg[2], 0);
    moe_gemm<H_DIM, true><<<grid1, 256, GEMM_SMEM, sw>>>(12);  // G1 g3
    cudaEventRecord(eg[3], sw);

    cudaStreamWaitEvent(sw, eg[0], 0);
    moe_gemm<I_DIM, false><<<grid2, 256, GEMM_SMEM, sw>>>(0);  // G2 g0
    cudaStreamWaitEvent(0, eg[1], 0);
    moe_gemm<I_DIM, false><<<grid2, 256, GEMM_SMEM, 0>>>(4);   // G2 g1
    cudaStreamWaitEvent(sw, eg[2], 0);
    moe_gemm<I_DIM, false><<<grid2, 256, GEMM_SMEM, sw>>>(8);  // G2 g2
    cudaEventRecord(evS, sw);
    cudaStreamWaitEvent(0, eg[3], 0);
    moe_gemm<I_DIM, false><<<grid2, 256, GEMM_SMEM, 0>>>(12);  // G2 g3

    // ---- combine: needs all G2 groups --------------------------------------
    cudaStreamWaitEvent(0, evS, 0);
    int nc = T_TOK * (H_DIM / 8);
    combine_kernel<<<(nc + 255) / 256, 256>>>(out);
}